// round 7
// baseline (speedup 1.0000x reference)
#include <cuda_runtime.h>
#include <cuda_bf16.h>
#include <cstdint>

// ---------------- problem constants ----------------
#define BSZ        4
#define DIM        512
#define D_INNER    1024
#define HEADDIM    128
#define NHEADS     8
#define D_STATE    128
#define D_CONV     4
#define CONV_DIM   1280          // D_INNER + 2*D_STATE
#define D_IN_PROJ  2312          // 2*D_INNER + 2*D_STATE + NHEADS
#define LSEQ       4096          // 16*16*16
#define NBL        (BSZ * LSEQ)  // 16384 rows (b,l)
#define NC         8             // scan chunks
#define CHUNK      (LSEQ / NC)   // 512 steps per chunk

// ---------------- device scratch (static globals; no allocation) ----------------
__device__ __align__(128) float  g_zx  [(size_t)NBL * D_IN_PROJ];   // in_proj out (z | xBC | dt_raw)
__device__ __align__(128) float  g_conv[(size_t)NBL * CONV_DIM];    // conv+silu out (xs | B | C)
__device__ __align__(128) float2 g_dtdA[NBL * NHEADS];              // (dt, exp(dt*A)) packed
__device__ __align__(128) float  g_y   [(size_t)NBL * D_INNER];     // scan out, normed in-place
__device__ __align__(128) float  g_S   [(size_t)32 * NC * HEADDIM * D_STATE]; // chunk states (16MB)
__device__ __align__(128) float  g_cumP[NBL * NHEADS];              // within-chunk cumprod of dA

// ---------------- f32x2 packed helpers ----------------
__device__ __forceinline__ uint64_t pack2(float lo, float hi) {
    uint64_t r; asm("mov.b64 %0, {%1, %2};" : "=l"(r) : "f"(lo), "f"(hi)); return r;
}
__device__ __forceinline__ void unpack2(uint64_t v, float& lo, float& hi) {
    asm("mov.b64 {%0, %1}, %2;" : "=f"(lo), "=f"(hi) : "l"(v));
}
__device__ __forceinline__ uint64_t fma2(uint64_t a, uint64_t b, uint64_t c) {
    uint64_t d; asm("fma.rn.f32x2 %0, %1, %2, %3;" : "=l"(d) : "l"(a), "l"(b), "l"(c)); return d;
}
__device__ __forceinline__ uint64_t mul2(uint64_t a, uint64_t b) {
    uint64_t d; asm("mul.rn.f32x2 %0, %1, %2;" : "=l"(d) : "l"(a), "l"(b)); return d;
}
// Reduce 4 per-thread values over 32 lanes with 6 shuffles.
// Returns: lane j (j = lane & 3) holds full sum of v_j.
__device__ __forceinline__ float reduce4(float v0, float v1, float v2, float v3, int lane) {
    float a = (lane & 1) ? v1 : v0;
    float b = (lane & 1) ? v0 : v1;
    a += __shfl_xor_sync(0xffffffffu, b, 1);
    float c = (lane & 1) ? v3 : v2;
    float d = (lane & 1) ? v2 : v3;
    c += __shfl_xor_sync(0xffffffffu, d, 1);
    float e = (lane & 2) ? c : a;
    float f = (lane & 2) ? a : c;
    e += __shfl_xor_sync(0xffffffffu, f, 2);
    e += __shfl_xor_sync(0xffffffffu, e, 4);
    e += __shfl_xor_sync(0xffffffffu, e, 8);
    e += __shfl_xor_sync(0xffffffffu, e, 16);
    return e;
}

// =====================================================================
// GEMM1: zxbcdt[m][n] = sum_k x[b][k][l] * W[n][k],  m = b*4096 + l
// =====================================================================
__global__ __launch_bounds__(256) void gemm1_kernel(const float* __restrict__ x,
                                                    const float* __restrict__ W) {
    __shared__ float As[8][128];    // [k][m]
    __shared__ float Bs[8][132];    // [k][n] (padded)
    const int tid = threadIdx.x;
    const int m0  = blockIdx.y * 128;
    const int n0  = blockIdx.x * 128;
    const int b   = m0 >> 12;
    const int l0  = m0 & 4095;
    const float* Ap = x + (size_t)b * DIM * LSEQ + l0;   // + k*4096 + m_local

    const int tx = tid & 15, ty = tid >> 4;
    const int ka = tid >> 5;            // 0..7
    const int ma = (tid & 31) * 4;      // 0..124
    const int nb = tid >> 1;            // 0..127
    const int kb = (tid & 1) * 4;       // 0 or 4

    const int nglob = n0 + nb;
    const bool nval = (nglob < D_IN_PROJ);

    float acc[8][8];
#pragma unroll
    for (int i = 0; i < 8; i++)
#pragma unroll
        for (int j = 0; j < 8; j++) acc[i][j] = 0.f;

    for (int k0 = 0; k0 < DIM; k0 += 8) {
        float4 av = *(const float4*)(Ap + (size_t)(k0 + ka) * LSEQ + ma);
        float4 bv = make_float4(0.f, 0.f, 0.f, 0.f);
        if (nval) bv = *(const float4*)(W + (size_t)nglob * DIM + k0 + kb);
        *(float4*)&As[ka][ma] = av;
        Bs[kb + 0][nb] = bv.x; Bs[kb + 1][nb] = bv.y;
        Bs[kb + 2][nb] = bv.z; Bs[kb + 3][nb] = bv.w;
        __syncthreads();
#pragma unroll
        for (int kk = 0; kk < 8; kk++) {
            float a[8], bb[8];
            *(float4*)&a[0]  = *(float4*)&As[kk][ty * 8];
            *(float4*)&a[4]  = *(float4*)&As[kk][ty * 8 + 4];
            *(float4*)&bb[0] = *(float4*)&Bs[kk][tx * 8];
            *(float4*)&bb[4] = *(float4*)&Bs[kk][tx * 8 + 4];
#pragma unroll
            for (int i = 0; i < 8; i++)
#pragma unroll
                for (int j = 0; j < 8; j++)
                    acc[i][j] = fmaf(a[i], bb[j], acc[i][j]);
        }
        __syncthreads();
    }

    const bool full = (n0 + 128 <= D_IN_PROJ);
#pragma unroll
    for (int i = 0; i < 8; i++) {
        const int m = m0 + ty * 8 + i;
        float* op = g_zx + (size_t)m * D_IN_PROJ + n0 + tx * 8;
        if (full) {
            *(float4*)op       = make_float4(acc[i][0], acc[i][1], acc[i][2], acc[i][3]);
            *(float4*)(op + 4) = make_float4(acc[i][4], acc[i][5], acc[i][6], acc[i][7]);
        } else {
#pragma unroll
            for (int j = 0; j < 8; j++)
                if (n0 + tx * 8 + j < D_IN_PROJ) op[j] = acc[i][j];
        }
    }
}

// =====================================================================
// prep: dt = softplus(dt_raw + dt_bias); dA = exp(dt * (-exp(A_log)))
// =====================================================================
__global__ __launch_bounds__(256) void prep_kernel(const float* __restrict__ dt_bias,
                                                   const float* __restrict__ A_log) {
    const int gid = blockIdx.x * 256 + threadIdx.x;   // < NBL*NHEADS = 131072
    const int bl = gid >> 3, h = gid & 7;
    float v = g_zx[(size_t)bl * D_IN_PROJ + (D_INNER + CONV_DIM) + h] + dt_bias[h];
    float dt = (v > 20.f) ? v : log1pf(expf(v));
    float A = -expf(A_log[h]);
    g_dtdA[gid] = make_float2(dt, expf(dt * A));
}

// =====================================================================
// conv: causal depthwise conv over l (width 4) + bias, then SiLU.
// =====================================================================
__global__ __launch_bounds__(256) void conv_kernel(const float* __restrict__ conv_w,
                                                   const float* __restrict__ conv_b) {
    const int gid = blockIdx.x * 256 + threadIdx.x;   // exactly NBL*CONV_DIM
    const int bl = gid / CONV_DIM;
    const int c  = gid - bl * CONV_DIM;
    const int l  = bl & 4095;
    const float w0 = conv_w[c * 4 + 0], w1 = conv_w[c * 4 + 1];
    const float w2 = conv_w[c * 4 + 2], w3 = conv_w[c * 4 + 3];
    const float* base = g_zx + (size_t)bl * D_IN_PROJ + D_INNER + c;
    float acc = conv_b[c];
    if (l >= 3) {
        acc += base[-3 * D_IN_PROJ] * w0;
        acc += base[-2 * D_IN_PROJ] * w1;
        acc += base[-1 * D_IN_PROJ] * w2;
        acc += base[0] * w3;
    } else {
        if (l >= 2) acc += base[-2 * D_IN_PROJ] * w1;
        if (l >= 1) acc += base[-1 * D_IN_PROJ] * w2;
        acc += base[0] * w3;
    }
    g_conv[gid] = acc / (1.f + expf(-acc));
}

// =====================================================================
// cumP: within-chunk running product of dA. 256 chains (b,h,chunk).
// =====================================================================
__global__ void cumP_kernel() {
    const int chain = blockIdx.x * 32 + threadIdx.x;   // 0..255
    const int bh = chain >> 3, c = chain & 7;
    const int b = bh >> 3, h = bh & 7;
    const int blbase = b << 12;
    const int t0 = c * CHUNK;
    float p = 1.f;
#pragma unroll 4
    for (int t = t0; t < t0 + CHUNK; t++) {
        p *= g_dtdA[(blbase + t) * NHEADS + h].y;
        g_cumP[(blbase + t) * NHEADS + h] = p;
    }
}

// =====================================================================
// scan pass A: chunked local scan. Grid (pt:8, c:8, bh:32) = 2048 blocks,
// 128 threads = 4 warps; warp w owns p rows [pt*16+4w, +4); lane owns
// n-slice [lane*4, +4) as 2 packed f32x2 per p. Depth-4 prefetch.
// Writes local y (+ D skip) and final local chunk state to g_S.
// =====================================================================
#define SCAN_LD(buf, t) do {                                                  \
    const float* _br = Bp + (size_t)(t) * CONV_DIM;                           \
    B##buf = *(const ulonglong2*)_br;                                         \
    C##buf = *(const ulonglong2*)(_br + D_STATE);                             \
    x##buf = *(const float4*)(Xp + (size_t)(t) * CONV_DIM);                   \
    dd##buf = DDp[(t) * NHEADS];                                              \
} while (0)

#define SCAN_P(buf, p, xi, vout) do {                                         \
    const float _dtx = (xi) * dd##buf.x;                                      \
    const uint64_t _dtx2 = pack2(_dtx, _dtx);                                 \
    s##p##0 = fma2(B##buf.x, _dtx2, mul2(s##p##0, _dA2));                     \
    s##p##1 = fma2(B##buf.y, _dtx2, mul2(s##p##1, _dA2));                     \
    uint64_t _y2 = fma2(s##p##1, C##buf.y, mul2(s##p##0, C##buf.x));          \
    float _lo, _hi; unpack2(_y2, _lo, _hi);                                   \
    vout = _lo + _hi;                                                         \
} while (0)

#define SCAN_STEP(buf, t) do {                                                \
    const uint64_t _dA2 = pack2(dd##buf.y, dd##buf.y);                        \
    float v0, v1, v2, v3;                                                     \
    SCAN_P(buf, 0, x##buf.x, v0);                                             \
    SCAN_P(buf, 1, x##buf.y, v1);                                             \
    SCAN_P(buf, 2, x##buf.z, v2);                                             \
    SCAN_P(buf, 3, x##buf.w, v3);                                             \
    float _e = reduce4(v0, v1, v2, v3, lane);                                 \
    if (lane < 4) {                                                           \
        float _xs = (lane == 0) ? x##buf.x : (lane == 1) ? x##buf.y           \
                  : (lane == 2) ? x##buf.z : x##buf.w;                        \
        Yp[(size_t)(t) * D_INNER + lane] = _e + Dh * _xs;                     \
    }                                                                         \
} while (0)

__global__ __launch_bounds__(128, 5) void scan_kernel(const float* __restrict__ D_param) {
    const int tid  = threadIdx.x;
    const int lane = tid & 31;
    const int w    = tid >> 5;          // 0..3
    const int pt = blockIdx.x;          // 0..7
    const int c  = blockIdx.y;          // 0..7
    const int bh = blockIdx.z;          // 0..31
    const int b = bh >> 3, h = bh & 7;
    const int p0 = pt * 16 + w * 4;
    const int n0 = lane * 4;
    const float Dh = D_param[h];
    const int blbase = b << 12;
    const int t0 = c * CHUNK, tend = t0 + CHUNK;

    const float* Bp = g_conv + (size_t)blbase * CONV_DIM + D_INNER + n0;
    const float* Xp = g_conv + (size_t)blbase * CONV_DIM + h * HEADDIM + p0;
    const float2* DDp = g_dtdA + blbase * NHEADS + h;
    float* Yp = g_y + (size_t)blbase * D_INNER + h * HEADDIM + p0;

    uint64_t s00 = 0, s01 = 0, s10 = 0, s11 = 0;
    uint64_t s20 = 0, s21 = 0, s30 = 0, s31 = 0;

    ulonglong2 B0, C0, B1, C1, B2, C2, B3, C3;
    float4 x0, x1, x2, x3;
    float2 dd0, dd1, dd2, dd3;

    SCAN_LD(0, t0);
    SCAN_LD(1, t0 + 1);
    SCAN_LD(2, t0 + 2);
    SCAN_LD(3, t0 + 3);
    for (int t = t0; t < tend; t += 4) {
        SCAN_STEP(0, t);
        SCAN_LD(0, min(t + 4, tend - 1));
        SCAN_STEP(1, t + 1);
        SCAN_LD(1, min(t + 5, tend - 1));
        SCAN_STEP(2, t + 2);
        SCAN_LD(2, min(t + 6, tend - 1));
        SCAN_STEP(3, t + 3);
        SCAN_LD(3, min(t + 7, tend - 1));
    }

    // store final local chunk state: thread covers 4p x 4n
    float* sp = g_S + ((size_t)(bh * NC + c) * HEADDIM + p0) * D_STATE + n0;
    { ulonglong2 r; r.x = s00; r.y = s01; *(ulonglong2*)(sp)              = r; }
    { ulonglong2 r; r.x = s10; r.y = s11; *(ulonglong2*)(sp + D_STATE)     = r; }
    { ulonglong2 r; r.x = s20; r.y = s21; *(ulonglong2*)(sp + 2 * D_STATE) = r; }
    { ulonglong2 r; r.x = s30; r.y = s31; *(ulonglong2*)(sp + 3 * D_STATE) = r; }
}

// =====================================================================
// pass B: chunk carry recurrence. S_in_{c+1} = SL_c + Ptot_c * S_in_c.
// Overwrites g_S[c] with carry-in state S_in_c. 131072 threads.
// =====================================================================
__global__ __launch_bounds__(256) void passB_kernel() {
    const int gid = blockIdx.x * 256 + threadIdx.x;
    const int n0 = (gid & 31) * 4;
    const int p  = (gid >> 5) & 127;
    const int bh = gid >> 12;
    const int b = bh >> 3, h = bh & 7;
    const int blbase = b << 12;
    float4 carry = make_float4(0.f, 0.f, 0.f, 0.f);
#pragma unroll
    for (int c = 0; c < NC; c++) {
        float* sp = g_S + ((size_t)(bh * NC + c) * HEADDIM + p) * D_STATE + n0;
        float4 SL = *(float4*)sp;
        *(float4*)sp = carry;
        float Pt = g_cumP[(blbase + c * CHUNK + CHUNK - 1) * NHEADS + h];
        carry.x = SL.x + Pt * carry.x;
        carry.y = SL.y + Pt * carry.y;
        carry.z = SL.z + Pt * carry.z;
        carry.w = SL.w + Pt * carry.w;
    }
}

// =====================================================================
// pass C (fixup): y_t += cumP_t * (C_t · S_in_c). Chunks 1..7 only.
// Grid (pt:8, c-1:7, bh:32) = 1792 blocks, 128 threads; fully parallel
// over t, so throughput-bound.
// =====================================================================
__global__ __launch_bounds__(128) void fixup_kernel() {
    const int tid = threadIdx.x, lane = tid & 31, w = tid >> 5;
    const int pt = blockIdx.x;
    const int c  = blockIdx.y + 1;      // 1..7
    const int bh = blockIdx.z;
    const int b = bh >> 3, h = bh & 7;
    const int p0 = pt * 16 + w * 4, n0 = lane * 4;
    const int blbase = b << 12;
    const int t0 = c * CHUNK;

    uint64_t S00, S01, S10, S11, S20, S21, S30, S31;
    {
        const float* sp = g_S + ((size_t)(bh * NC + c) * HEADDIM + p0) * D_STATE + n0;
        ulonglong2 r0 = *(const ulonglong2*)(sp);
        ulonglong2 r1 = *(const ulonglong2*)(sp + D_STATE);
        ulonglong2 r2 = *(const ulonglong2*)(sp + 2 * D_STATE);
        ulonglong2 r3 = *(const ulonglong2*)(sp + 3 * D_STATE);
        S00 = r0.x; S01 = r0.y; S10 = r1.x; S11 = r1.y;
        S20 = r2.x; S21 = r2.y; S30 = r3.x; S31 = r3.y;
    }
    const float* Cp = g_conv + (size_t)blbase * CONV_DIM + D_INNER + D_STATE + n0;
    const float* Pp = g_cumP + blbase * NHEADS + h;
    float* Yp = g_y + (size_t)blbase * D_INNER + h * HEADDIM + p0;

#pragma unroll 2
    for (int t = t0; t < t0 + CHUNK; t++) {
        ulonglong2 Cv = *(const ulonglong2*)(Cp + (size_t)t * CONV_DIM);
        float cp = Pp[t * NHEADS];
        float v0, v1, v2, v3;
        { uint64_t u = fma2(S01, Cv.y, mul2(S00, Cv.x)); float lo, hi; unpack2(u, lo, hi); v0 = lo + hi; }
        { uint64_t u = fma2(S11, Cv.y, mul2(S10, Cv.x)); float lo, hi; unpack2(u, lo, hi); v1 = lo + hi; }
        { uint64_t u = fma2(S21, Cv.y, mul2(S20, Cv.x)); float lo, hi; unpack2(u, lo, hi); v2 = lo + hi; }
        { uint64_t u = fma2(S31, Cv.y, mul2(S30, Cv.x)); float lo, hi; unpack2(u, lo, hi); v3 = lo + hi; }
        float e = reduce4(v0, v1, v2, v3, lane);
        if (lane < 4) {
            float* yp = Yp + (size_t)t * D_INNER + lane;
            *yp += cp * e;
        }
    }
}

// =====================================================================
// mulnorm: y = y * silu(z); y = y * rsqrt(mean(y^2)+1e-5) * norm_w
// =====================================================================
__global__ __launch_bounds__(256) void mulnorm_kernel(const float* __restrict__ norm_w) {
    __shared__ float red[8];
    __shared__ float rinv;
    const int bl = blockIdx.x, tid = threadIdx.x;
    const int lane = tid & 31, w = tid >> 5;
    float4 yv = *(const float4*)(g_y + (size_t)bl * D_INNER + tid * 4);
    float4 zv = *(const float4*)(g_zx + (size_t)bl * D_IN_PROJ + tid * 4);
    float4 t;
    t.x = yv.x * (zv.x / (1.f + expf(-zv.x)));
    t.y = yv.y * (zv.y / (1.f + expf(-zv.y)));
    t.z = yv.z * (zv.z / (1.f + expf(-zv.z)));
    t.w = yv.w * (zv.w / (1.f + expf(-zv.w)));
    float ss = t.x * t.x + t.y * t.y + t.z * t.z + t.w * t.w;
#pragma unroll
    for (int off = 16; off > 0; off >>= 1) ss += __shfl_xor_sync(0xffffffffu, ss, off);
    if (lane == 0) red[w] = ss;
    __syncthreads();
    if (tid == 0) {
        float tot = 0.f;
#pragma unroll
        for (int i = 0; i < 8; i++) tot += red[i];
        rinv = rsqrtf(tot * (1.f / (float)D_INNER) + 1e-5f);
    }
    __syncthreads();
    const float r = rinv;
    float4 w4 = *(const float4*)(norm_w + tid * 4);
    t.x *= r * w4.x; t.y *= r * w4.y; t.z *= r * w4.z; t.w *= r * w4.w;
    *(float4*)(g_y + (size_t)bl * D_INNER + tid * 4) = t;
}

// =====================================================================
// GEMM2: out[b][d][l] = sum_e Wo[d][e] * y[b*4096+l][e] + x[b][d][l]
// =====================================================================
__global__ __launch_bounds__(256) void gemm2_kernel(const float* __restrict__ Wo,
                                                    const float* __restrict__ x,
                                                    float* __restrict__ out) {
    __shared__ float As[8][132];   // [k][d]
    __shared__ float Bs[8][132];   // [k][l]
    const int tid = threadIdx.x;
    const int l0 = blockIdx.x * 128;
    const int d0 = blockIdx.y * 128;
    const int b  = blockIdx.z;
    const float* yp = g_y + (size_t)(b * LSEQ + l0) * D_INNER;

    const int tx = tid & 15, ty = tid >> 4;
    const int ra = tid >> 1;            // 0..127
    const int ka = (tid & 1) * 4;       // 0 or 4

    float acc[8][8];
#pragma unroll
    for (int i = 0; i < 8; i++)
#pragma unroll
        for (int j = 0; j < 8; j++) acc[i][j] = 0.f;

    for (int k0 = 0; k0 < D_INNER; k0 += 8) {
        float4 av = *(const float4*)(Wo + (size_t)(d0 + ra) * D_INNER + k0 + ka);
        float4 bv = *(const float4*)(yp + (size_t)ra * D_INNER + k0 + ka);
        As[ka + 0][ra] = av.x; As[ka + 1][ra] = av.y;
        As[ka + 2][ra] = av.z; As[ka + 3][ra] = av.w;
        Bs[ka + 0][ra] = bv.x; Bs[ka + 1][ra] = bv.y;
        Bs[ka + 2][ra] = bv.z; Bs[ka + 3][ra] = bv.w;
        __syncthreads();
#pragma unroll
        for (int kk = 0; kk < 8; kk++) {
            float a[8], bb[8];
            *(float4*)&a[0]  = *(float4*)&As[kk][ty * 8];
            *(float4*)&a[4]  = *(float4*)&As[kk][ty * 8 + 4];
            *(float4*)&bb[0] = *(float4*)&Bs[kk][tx * 8];
            *(float4*)&bb[4] = *(float4*)&Bs[kk][tx * 8 + 4];
#pragma unroll
            for (int i = 0; i < 8; i++)
#pragma unroll
                for (int j = 0; j < 8; j++)
                    acc[i][j] = fmaf(a[i], bb[j], acc[i][j]);
        }
        __syncthreads();
    }

    const size_t base = (size_t)b * DIM * LSEQ;
#pragma unroll
    for (int i = 0; i < 8; i++) {
        const int d = d0 + ty * 8 + i;
        const size_t off = base + (size_t)d * LSEQ + l0 + tx * 8;
        float4 x0 = *(const float4*)(x + off);
        float4 x1 = *(const float4*)(x + off + 4);
        float4 o0 = make_float4(acc[i][0] + x0.x, acc[i][1] + x0.y,
                                acc[i][2] + x0.z, acc[i][3] + x0.w);
        float4 o1 = make_float4(acc[i][4] + x1.x, acc[i][5] + x1.y,
                                acc[i][6] + x1.z, acc[i][7] + x1.w);
        *(float4*)(out + off)     = o0;
        *(float4*)(out + off + 4) = o1;
    }
}

// =====================================================================
extern "C" void kernel_launch(void* const* d_in, const int* in_sizes, int n_in,
                              void* d_out, int out_size) {
    const float* x          = (const float*)d_in[0];
    const float* in_proj_w  = (const float*)d_in[1];
    const float* conv_w     = (const float*)d_in[2];
    const float* conv_b     = (const float*)d_in[3];
    const float* dt_bias    = (const float*)d_in[4];
    const float* A_log      = (const float*)d_in[5];
    const float* D_param    = (const float*)d_in[6];
    const float* norm_w     = (const float*)d_in[7];
    const float* out_proj_w = (const float*)d_in[8];
    float* out = (float*)d_out;

    // 1. in_proj GEMM
    gemm1_kernel<<<dim3((D_IN_PROJ + 127) / 128, NBL / 128), 256>>>(x, in_proj_w);
    // 2. dt softplus + dA packed
    prep_kernel<<<(NBL * NHEADS) / 256, 256>>>(dt_bias, A_log);
    // 3. depthwise causal conv + SiLU
    conv_kernel<<<((size_t)NBL * CONV_DIM) / 256, 256>>>(conv_w, conv_b);
    // 4a. within-chunk cumprod of dA
    cumP_kernel<<<8, 32>>>();
    // 4b. chunked local scan (pass A)
    scan_kernel<<<dim3(8, NC, 32), 128>>>(D_param);
    // 4c. chunk carry recurrence (pass B)
    passB_kernel<<<(32 * HEADDIM * D_STATE / 4) / 256, 256>>>();
    // 4d. carry fixup of y (pass C)
    fixup_kernel<<<dim3(8, NC - 1, 32), 128>>>();
    // 5. gate + RMSNorm
    mulnorm_kernel<<<NBL, 256>>>(norm_w);
    // 6. out_proj GEMM + residual, transposed store
    gemm2_kernel<<<dim3(LSEQ / 128, DIM / 128, BSZ), 256>>>(out_proj_w, x, out);
}

// round 8
// speedup vs baseline: 1.0810x; 1.0810x over previous
#include <cuda_runtime.h>
#include <cuda_bf16.h>
#include <cstdint>

// ---------------- problem constants ----------------
#define BSZ        4
#define DIM        512
#define D_INNER    1024
#define HEADDIM    128
#define NHEADS     8
#define D_STATE    128
#define D_CONV     4
#define CONV_DIM   1280          // D_INNER + 2*D_STATE
#define D_IN_PROJ  2312          // 2*D_INNER + 2*D_STATE + NHEADS
#define LSEQ       4096          // 16*16*16
#define NBL        (BSZ * LSEQ)  // 16384 rows (b,l)
#define NC         8             // scan chunks
#define CHUNK      (LSEQ / NC)   // 512 steps per chunk

// ---------------- device scratch (static globals; no allocation) ----------------
__device__ __align__(128) float  g_zx  [(size_t)NBL * D_IN_PROJ];   // in_proj out (z | xBC | dt_raw)
__device__ __align__(128) float  g_conv[(size_t)NBL * CONV_DIM];    // conv+silu out (xs | B | C)
__device__ __align__(128) float2 g_dtdA[NBL * NHEADS];              // (dt, exp(dt*A)) packed
__device__ __align__(128) float  g_y   [(size_t)NBL * D_INNER];     // scan out, normed in-place
__device__ __align__(128) float  g_S   [(size_t)32 * NC * HEADDIM * D_STATE]; // chunk states (16MB)
__device__ __align__(128) float  g_cumP[NBL * NHEADS];              // within-chunk cumprod of dA

// ---------------- f32x2 packed helpers ----------------
__device__ __forceinline__ uint64_t pack2(float lo, float hi) {
    uint64_t r; asm("mov.b64 %0, {%1, %2};" : "=l"(r) : "f"(lo), "f"(hi)); return r;
}
__device__ __forceinline__ void unpack2(uint64_t v, float& lo, float& hi) {
    asm("mov.b64 {%0, %1}, %2;" : "=f"(lo), "=f"(hi) : "l"(v));
}
__device__ __forceinline__ uint64_t fma2(uint64_t a, uint64_t b, uint64_t c) {
    uint64_t d; asm("fma.rn.f32x2 %0, %1, %2, %3;" : "=l"(d) : "l"(a), "l"(b), "l"(c)); return d;
}
__device__ __forceinline__ uint64_t mul2(uint64_t a, uint64_t b) {
    uint64_t d; asm("mul.rn.f32x2 %0, %1, %2;" : "=l"(d) : "l"(a), "l"(b)); return d;
}
// Reduce 4 per-thread values over 32 lanes with 6 shuffles.
// Returns: lane j (j = lane & 3) holds full sum of v_j.
__device__ __forceinline__ float reduce4(float v0, float v1, float v2, float v3, int lane) {
    float a = (lane & 1) ? v1 : v0;
    float b = (lane & 1) ? v0 : v1;
    a += __shfl_xor_sync(0xffffffffu, b, 1);
    float c = (lane & 1) ? v3 : v2;
    float d = (lane & 1) ? v2 : v3;
    c += __shfl_xor_sync(0xffffffffu, d, 1);
    float e = (lane & 2) ? c : a;
    float f = (lane & 2) ? a : c;
    e += __shfl_xor_sync(0xffffffffu, f, 2);
    e += __shfl_xor_sync(0xffffffffu, e, 4);
    e += __shfl_xor_sync(0xffffffffu, e, 8);
    e += __shfl_xor_sync(0xffffffffu, e, 16);
    return e;
}

// =====================================================================
// GEMM1: zxbcdt[m][n] = sum_k x[b][k][l] * W[n][k],  m = b*4096 + l
// f32x2-packed inner loop: j-dim paired, 32 fma2 + 8 pack per kk.
// =====================================================================
__global__ __launch_bounds__(256) void gemm1_kernel(const float* __restrict__ x,
                                                    const float* __restrict__ W) {
    __shared__ float As[8][128];    // [k][m]
    __shared__ float Bs[8][132];    // [k][n] (row stride 528B = 16B-aligned)
    const int tid = threadIdx.x;
    const int m0  = blockIdx.y * 128;
    const int n0  = blockIdx.x * 128;
    const int b   = m0 >> 12;
    const int l0  = m0 & 4095;
    const float* Ap = x + (size_t)b * DIM * LSEQ + l0;   // + k*4096 + m_local

    const int tx = tid & 15, ty = tid >> 4;
    const int ka = tid >> 5;            // 0..7
    const int ma = (tid & 31) * 4;      // 0..124
    const int nb = tid >> 1;            // 0..127
    const int kb = (tid & 1) * 4;       // 0 or 4

    const int nglob = n0 + nb;
    const bool nval = (nglob < D_IN_PROJ);

    uint64_t acc2[8][4];
#pragma unroll
    for (int i = 0; i < 8; i++)
#pragma unroll
        for (int j = 0; j < 4; j++) acc2[i][j] = 0;

    for (int k0 = 0; k0 < DIM; k0 += 8) {
        float4 av = *(const float4*)(Ap + (size_t)(k0 + ka) * LSEQ + ma);
        float4 bv = make_float4(0.f, 0.f, 0.f, 0.f);
        if (nval) bv = *(const float4*)(W + (size_t)nglob * DIM + k0 + kb);
        *(float4*)&As[ka][ma] = av;
        Bs[kb + 0][nb] = bv.x; Bs[kb + 1][nb] = bv.y;
        Bs[kb + 2][nb] = bv.z; Bs[kb + 3][nb] = bv.w;
        __syncthreads();
#pragma unroll
        for (int kk = 0; kk < 8; kk++) {
            float a[8];
            *(float4*)&a[0]  = *(float4*)&As[kk][ty * 8];
            *(float4*)&a[4]  = *(float4*)&As[kk][ty * 8 + 4];
            ulonglong2 b0 = *(ulonglong2*)&Bs[kk][tx * 8];
            ulonglong2 b1 = *(ulonglong2*)&Bs[kk][tx * 8 + 4];
#pragma unroll
            for (int i = 0; i < 8; i++) {
                const uint64_t a2 = pack2(a[i], a[i]);
                acc2[i][0] = fma2(a2, b0.x, acc2[i][0]);
                acc2[i][1] = fma2(a2, b0.y, acc2[i][1]);
                acc2[i][2] = fma2(a2, b1.x, acc2[i][2]);
                acc2[i][3] = fma2(a2, b1.y, acc2[i][3]);
            }
        }
        __syncthreads();
    }

    const bool full = (n0 + 128 <= D_IN_PROJ);
#pragma unroll
    for (int i = 0; i < 8; i++) {
        float acc[8];
        unpack2(acc2[i][0], acc[0], acc[1]);
        unpack2(acc2[i][1], acc[2], acc[3]);
        unpack2(acc2[i][2], acc[4], acc[5]);
        unpack2(acc2[i][3], acc[6], acc[7]);
        const int m = m0 + ty * 8 + i;
        float* op = g_zx + (size_t)m * D_IN_PROJ + n0 + tx * 8;
        if (full) {
            *(float4*)op       = make_float4(acc[0], acc[1], acc[2], acc[3]);
            *(float4*)(op + 4) = make_float4(acc[4], acc[5], acc[6], acc[7]);
        } else {
#pragma unroll
            for (int j = 0; j < 8; j++)
                if (n0 + tx * 8 + j < D_IN_PROJ) op[j] = acc[j];
        }
    }
}

// =====================================================================
// prep: dt = softplus(dt_raw + dt_bias); dA = exp(dt * (-exp(A_log)))
// =====================================================================
__global__ __launch_bounds__(256) void prep_kernel(const float* __restrict__ dt_bias,
                                                   const float* __restrict__ A_log) {
    const int gid = blockIdx.x * 256 + threadIdx.x;   // < NBL*NHEADS = 131072
    const int bl = gid >> 3, h = gid & 7;
    float v = g_zx[(size_t)bl * D_IN_PROJ + (D_INNER + CONV_DIM) + h] + dt_bias[h];
    float dt = (v > 20.f) ? v : log1pf(expf(v));
    float A = -expf(A_log[h]);
    g_dtdA[gid] = make_float2(dt, expf(dt * A));
}

// =====================================================================
// conv: causal depthwise conv over l (width 4) + bias, then SiLU.
// =====================================================================
__global__ __launch_bounds__(256) void conv_kernel(const float* __restrict__ conv_w,
                                                   const float* __restrict__ conv_b) {
    const int gid = blockIdx.x * 256 + threadIdx.x;   // exactly NBL*CONV_DIM
    const int bl = gid / CONV_DIM;
    const int c  = gid - bl * CONV_DIM;
    const int l  = bl & 4095;
    const float w0 = conv_w[c * 4 + 0], w1 = conv_w[c * 4 + 1];
    const float w2 = conv_w[c * 4 + 2], w3 = conv_w[c * 4 + 3];
    const float* base = g_zx + (size_t)bl * D_IN_PROJ + D_INNER + c;
    float acc = conv_b[c];
    if (l >= 3) {
        acc += base[-3 * D_IN_PROJ] * w0;
        acc += base[-2 * D_IN_PROJ] * w1;
        acc += base[-1 * D_IN_PROJ] * w2;
        acc += base[0] * w3;
    } else {
        if (l >= 2) acc += base[-2 * D_IN_PROJ] * w1;
        if (l >= 1) acc += base[-1 * D_IN_PROJ] * w2;
        acc += base[0] * w3;
    }
    g_conv[gid] = acc / (1.f + expf(-acc));
}

// =====================================================================
// cumP v2: warp-parallel prefix product. 256 chains (b,h,chunk), one
// warp each; 16 elems/thread serial + 5-shuffle scan + local re-walk.
// Grid: 32 blocks x 256 threads (8 warps).
// =====================================================================
__global__ __launch_bounds__(256) void cumP_kernel() {
    const int gw   = blockIdx.x * 8 + (threadIdx.x >> 5);   // global warp 0..255
    const int lane = threadIdx.x & 31;
    const int bh = gw >> 3, c = gw & 7;
    const int b = bh >> 3, h = bh & 7;
    const int blbase = b << 12;
    const int tbase = c * CHUNK + lane * 16;

    float vals[16];
    float p = 1.f;
#pragma unroll
    for (int i = 0; i < 16; i++) {
        vals[i] = g_dtdA[(blbase + tbase + i) * NHEADS + h].y;
        p *= vals[i];
    }
    // inclusive scan (product) across lanes
    float scan = p;
#pragma unroll
    for (int off = 1; off < 32; off <<= 1) {
        float v = __shfl_up_sync(0xffffffffu, scan, off);
        if (lane >= off) scan *= v;
    }
    // exclusive prefix
    float excl = __shfl_up_sync(0xffffffffu, scan, 1);
    if (lane == 0) excl = 1.f;

    float run = excl;
#pragma unroll
    for (int i = 0; i < 16; i++) {
        run *= vals[i];
        g_cumP[(blbase + tbase + i) * NHEADS + h] = run;
    }
}

// =====================================================================
// scan pass A: chunked local scan. Grid (pt:8, c:8, bh:32) = 2048 blocks,
// 128 threads = 4 warps; warp w owns p rows [pt*16+4w, +4); lane owns
// n-slice [lane*4, +4) as 2 packed f32x2 per p. Depth-4 prefetch.
// Writes local y (+ D skip) and final local chunk state to g_S.
// =====================================================================
#define SCAN_LD(buf, t) do {                                                  \
    const float* _br = Bp + (size_t)(t) * CONV_DIM;                           \
    B##buf = *(const ulonglong2*)_br;                                         \
    C##buf = *(const ulonglong2*)(_br + D_STATE);                             \
    x##buf = *(const float4*)(Xp + (size_t)(t) * CONV_DIM);                   \
    dd##buf = DDp[(t) * NHEADS];                                              \
} while (0)

#define SCAN_P(buf, p, xi, vout) do {                                         \
    const float _dtx = (xi) * dd##buf.x;                                      \
    const uint64_t _dtx2 = pack2(_dtx, _dtx);                                 \
    s##p##0 = fma2(B##buf.x, _dtx2, mul2(s##p##0, _dA2));                     \
    s##p##1 = fma2(B##buf.y, _dtx2, mul2(s##p##1, _dA2));                     \
    uint64_t _y2 = fma2(s##p##1, C##buf.y, mul2(s##p##0, C##buf.x));          \
    float _lo, _hi; unpack2(_y2, _lo, _hi);                                   \
    vout = _lo + _hi;                                                         \
} while (0)

#define SCAN_STEP(buf, t) do {                                                \
    const uint64_t _dA2 = pack2(dd##buf.y, dd##buf.y);                        \
    float v0, v1, v2, v3;                                                     \
    SCAN_P(buf, 0, x##buf.x, v0);                                             \
    SCAN_P(buf, 1, x##buf.y, v1);                                             \
    SCAN_P(buf, 2, x##buf.z, v2);                                             \
    SCAN_P(buf, 3, x##buf.w, v3);                                             \
    float _e = reduce4(v0, v1, v2, v3, lane);                                 \
    if (lane < 4) {                                                           \
        float _xs = (lane == 0) ? x##buf.x : (lane == 1) ? x##buf.y           \
                  : (lane == 2) ? x##buf.z : x##buf.w;                        \
        Yp[(size_t)(t) * D_INNER + lane] = _e + Dh * _xs;                     \
    }                                                                         \
} while (0)

__global__ __launch_bounds__(128, 5) void scan_kernel(const float* __restrict__ D_param) {
    const int tid  = threadIdx.x;
    const int lane = tid & 31;
    const int w    = tid >> 5;          // 0..3
    const int pt = blockIdx.x;          // 0..7
    const int c  = blockIdx.y;          // 0..7
    const int bh = blockIdx.z;          // 0..31
    const int b = bh >> 3, h = bh & 7;
    const int p0 = pt * 16 + w * 4;
    const int n0 = lane * 4;
    const float Dh = D_param[h];
    const int blbase = b << 12;
    const int t0 = c * CHUNK, tend = t0 + CHUNK;

    const float* Bp = g_conv + (size_t)blbase * CONV_DIM + D_INNER + n0;
    const float* Xp = g_conv + (size_t)blbase * CONV_DIM + h * HEADDIM + p0;
    const float2* DDp = g_dtdA + blbase * NHEADS + h;
    float* Yp = g_y + (size_t)blbase * D_INNER + h * HEADDIM + p0;

    uint64_t s00 = 0, s01 = 0, s10 = 0, s11 = 0;
    uint64_t s20 = 0, s21 = 0, s30 = 0, s31 = 0;

    ulonglong2 B0, C0, B1, C1, B2, C2, B3, C3;
    float4 x0, x1, x2, x3;
    float2 dd0, dd1, dd2, dd3;

    SCAN_LD(0, t0);
    SCAN_LD(1, t0 + 1);
    SCAN_LD(2, t0 + 2);
    SCAN_LD(3, t0 + 3);
    for (int t = t0; t < tend; t += 4) {
        SCAN_STEP(0, t);
        SCAN_LD(0, min(t + 4, tend - 1));
        SCAN_STEP(1, t + 1);
        SCAN_LD(1, min(t + 5, tend - 1));
        SCAN_STEP(2, t + 2);
        SCAN_LD(2, min(t + 6, tend - 1));
        SCAN_STEP(3, t + 3);
        SCAN_LD(3, min(t + 7, tend - 1));
    }

    // store final local chunk state: thread covers 4p x 4n
    float* sp = g_S + ((size_t)(bh * NC + c) * HEADDIM + p0) * D_STATE + n0;
    { ulonglong2 r; r.x = s00; r.y = s01; *(ulonglong2*)(sp)              = r; }
    { ulonglong2 r; r.x = s10; r.y = s11; *(ulonglong2*)(sp + D_STATE)     = r; }
    { ulonglong2 r; r.x = s20; r.y = s21; *(ulonglong2*)(sp + 2 * D_STATE) = r; }
    { ulonglong2 r; r.x = s30; r.y = s31; *(ulonglong2*)(sp + 3 * D_STATE) = r; }
}

// =====================================================================
// pass B: chunk carry recurrence. S_in_{c+1} = SL_c + Ptot_c * S_in_c.
// Overwrites g_S[c] with carry-in state S_in_c. 131072 threads.
// =====================================================================
__global__ __launch_bounds__(256) void passB_kernel() {
    const int gid = blockIdx.x * 256 + threadIdx.x;
    const int n0 = (gid & 31) * 4;
    const int p  = (gid >> 5) & 127;
    const int bh = gid >> 12;
    const int b = bh >> 3, h = bh & 7;
    const int blbase = b << 12;
    float4 carry = make_float4(0.f, 0.f, 0.f, 0.f);
#pragma unroll
    for (int c = 0; c < NC; c++) {
        float* sp = g_S + ((size_t)(bh * NC + c) * HEADDIM + p) * D_STATE + n0;
        float4 SL = *(float4*)sp;
        *(float4*)sp = carry;
        float Pt = g_cumP[(blbase + c * CHUNK + CHUNK - 1) * NHEADS + h];
        carry.x = SL.x + Pt * carry.x;
        carry.y = SL.y + Pt * carry.y;
        carry.z = SL.z + Pt * carry.z;
        carry.w = SL.w + Pt * carry.w;
    }
}

// =====================================================================
// pass C (fixup): y_t += cumP_t * (C_t · S_in_c). Chunks 1..7 only.
// =====================================================================
__global__ __launch_bounds__(128) void fixup_kernel() {
    const int tid = threadIdx.x, lane = tid & 31, w = tid >> 5;
    const int pt = blockIdx.x;
    const int c  = blockIdx.y + 1;      // 1..7
    const int bh = blockIdx.z;
    const int b = bh >> 3, h = bh & 7;
    const int p0 = pt * 16 + w * 4, n0 = lane * 4;
    const int blbase = b << 12;
    const int t0 = c * CHUNK;

    uint64_t S00, S01, S10, S11, S20, S21, S30, S31;
    {
        const float* sp = g_S + ((size_t)(bh * NC + c) * HEADDIM + p0) * D_STATE + n0;
        ulonglong2 r0 = *(const ulonglong2*)(sp);
        ulonglong2 r1 = *(const ulonglong2*)(sp + D_STATE);
        ulonglong2 r2 = *(const ulonglong2*)(sp + 2 * D_STATE);
        ulonglong2 r3 = *(const ulonglong2*)(sp + 3 * D_STATE);
        S00 = r0.x; S01 = r0.y; S10 = r1.x; S11 = r1.y;
        S20 = r2.x; S21 = r2.y; S30 = r3.x; S31 = r3.y;
    }
    const float* Cp = g_conv + (size_t)blbase * CONV_DIM + D_INNER + D_STATE + n0;
    const float* Pp = g_cumP + blbase * NHEADS + h;
    float* Yp = g_y + (size_t)blbase * D_INNER + h * HEADDIM + p0;

#pragma unroll 2
    for (int t = t0; t < t0 + CHUNK; t++) {
        ulonglong2 Cv = *(const ulonglong2*)(Cp + (size_t)t * CONV_DIM);
        float cp = Pp[t * NHEADS];
        float v0, v1, v2, v3;
        { uint64_t u = fma2(S01, Cv.y, mul2(S00, Cv.x)); float lo, hi; unpack2(u, lo, hi); v0 = lo + hi; }
        { uint64_t u = fma2(S11, Cv.y, mul2(S10, Cv.x)); float lo, hi; unpack2(u, lo, hi); v1 = lo + hi; }
        { uint64_t u = fma2(S21, Cv.y, mul2(S20, Cv.x)); float lo, hi; unpack2(u, lo, hi); v2 = lo + hi; }
        { uint64_t u = fma2(S31, Cv.y, mul2(S30, Cv.x)); float lo, hi; unpack2(u, lo, hi); v3 = lo + hi; }
        float e = reduce4(v0, v1, v2, v3, lane);
        if (lane < 4) {
            float* yp = Yp + (size_t)t * D_INNER + lane;
            *yp += cp * e;
        }
    }
}

// =====================================================================
// mulnorm: y = y * silu(z); y = y * rsqrt(mean(y^2)+1e-5) * norm_w
// =====================================================================
__global__ __launch_bounds__(256) void mulnorm_kernel(const float* __restrict__ norm_w) {
    __shared__ float red[8];
    __shared__ float rinv;
    const int bl = blockIdx.x, tid = threadIdx.x;
    const int lane = tid & 31, w = tid >> 5;
    float4 yv = *(const float4*)(g_y + (size_t)bl * D_INNER + tid * 4);
    float4 zv = *(const float4*)(g_zx + (size_t)bl * D_IN_PROJ + tid * 4);
    float4 t;
    t.x = yv.x * (zv.x / (1.f + expf(-zv.x)));
    t.y = yv.y * (zv.y / (1.f + expf(-zv.y)));
    t.z = yv.z * (zv.z / (1.f + expf(-zv.z)));
    t.w = yv.w * (zv.w / (1.f + expf(-zv.w)));
    float ss = t.x * t.x + t.y * t.y + t.z * t.z + t.w * t.w;
#pragma unroll
    for (int off = 16; off > 0; off >>= 1) ss += __shfl_xor_sync(0xffffffffu, ss, off);
    if (lane == 0) red[w] = ss;
    __syncthreads();
    if (tid == 0) {
        float tot = 0.f;
#pragma unroll
        for (int i = 0; i < 8; i++) tot += red[i];
        rinv = rsqrtf(tot * (1.f / (float)D_INNER) + 1e-5f);
    }
    __syncthreads();
    const float r = rinv;
    float4 w4 = *(const float4*)(norm_w + tid * 4);
    t.x *= r * w4.x; t.y *= r * w4.y; t.z *= r * w4.z; t.w *= r * w4.w;
    *(float4*)(g_y + (size_t)bl * D_INNER + tid * 4) = t;
}

// =====================================================================
// GEMM2: out[b][d][l] = sum_e Wo[d][e] * y[b*4096+l][e] + x[b][d][l]
// f32x2-packed inner loop.
// =====================================================================
__global__ __launch_bounds__(256) void gemm2_kernel(const float* __restrict__ Wo,
                                                    const float* __restrict__ x,
                                                    float* __restrict__ out) {
    __shared__ float As[8][132];   // [k][d]
    __shared__ float Bs[8][132];   // [k][l]
    const int tid = threadIdx.x;
    const int l0 = blockIdx.x * 128;
    const int d0 = blockIdx.y * 128;
    const int b  = blockIdx.z;
    const float* yp = g_y + (size_t)(b * LSEQ + l0) * D_INNER;

    const int tx = tid & 15, ty = tid >> 4;
    const int ra = tid >> 1;            // 0..127
    const int ka = (tid & 1) * 4;       // 0 or 4

    uint64_t acc2[8][4];
#pragma unroll
    for (int i = 0; i < 8; i++)
#pragma unroll
        for (int j = 0; j < 4; j++) acc2[i][j] = 0;

    for (int k0 = 0; k0 < D_INNER; k0 += 8) {
        float4 av = *(const float4*)(Wo + (size_t)(d0 + ra) * D_INNER + k0 + ka);
        float4 bv = *(const float4*)(yp + (size_t)ra * D_INNER + k0 + ka);
        As[ka + 0][ra] = av.x; As[ka + 1][ra] = av.y;
        As[ka + 2][ra] = av.z; As[ka + 3][ra] = av.w;
        Bs[ka + 0][ra] = bv.x; Bs[ka + 1][ra] = bv.y;
        Bs[ka + 2][ra] = bv.z; Bs[ka + 3][ra] = bv.w;
        __syncthreads();
#pragma unroll
        for (int kk = 0; kk < 8; kk++) {
            float a[8];
            *(float4*)&a[0]  = *(float4*)&As[kk][ty * 8];
            *(float4*)&a[4]  = *(float4*)&As[kk][ty * 8 + 4];
            ulonglong2 b0 = *(ulonglong2*)&Bs[kk][tx * 8];
            ulonglong2 b1 = *(ulonglong2*)&Bs[kk][tx * 8 + 4];
#pragma unroll
            for (int i = 0; i < 8; i++) {
                const uint64_t a2 = pack2(a[i], a[i]);
                acc2[i][0] = fma2(a2, b0.x, acc2[i][0]);
                acc2[i][1] = fma2(a2, b0.y, acc2[i][1]);
                acc2[i][2] = fma2(a2, b1.x, acc2[i][2]);
                acc2[i][3] = fma2(a2, b1.y, acc2[i][3]);
            }
        }
        __syncthreads();
    }

    const size_t base = (size_t)b * DIM * LSEQ;
#pragma unroll
    for (int i = 0; i < 8; i++) {
        float acc[8];
        unpack2(acc2[i][0], acc[0], acc[1]);
        unpack2(acc2[i][1], acc[2], acc[3]);
        unpack2(acc2[i][2], acc[4], acc[5]);
        unpack2(acc2[i][3], acc[6], acc[7]);
        const int d = d0 + ty * 8 + i;
        const size_t off = base + (size_t)d * LSEQ + l0 + tx * 8;
        float4 x0 = *(const float4*)(x + off);
        float4 x1 = *(const float4*)(x + off + 4);
        float4 o0 = make_float4(acc[0] + x0.x, acc[1] + x0.y,
                                acc[2] + x0.z, acc[3] + x0.w);
        float4 o1 = make_float4(acc[4] + x1.x, acc[5] + x1.y,
                                acc[6] + x1.z, acc[7] + x1.w);
        *(float4*)(out + off)     = o0;
        *(float4*)(out + off + 4) = o1;
    }
}

// =====================================================================
extern "C" void kernel_launch(void* const* d_in, const int* in_sizes, int n_in,
                              void* d_out, int out_size) {
    const float* x          = (const float*)d_in[0];
    const float* in_proj_w  = (const float*)d_in[1];
    const float* conv_w     = (const float*)d_in[2];
    const float* conv_b     = (const float*)d_in[3];
    const float* dt_bias    = (const float*)d_in[4];
    const float* A_log      = (const float*)d_in[5];
    const float* D_param    = (const float*)d_in[6];
    const float* norm_w     = (const float*)d_in[7];
    const float* out_proj_w = (const float*)d_in[8];
    float* out = (float*)d_out;

    // 1. in_proj GEMM (f32x2 packed)
    gemm1_kernel<<<dim3((D_IN_PROJ + 127) / 128, NBL / 128), 256>>>(x, in_proj_w);
    // 2. dt softplus + dA packed
    prep_kernel<<<(NBL * NHEADS) / 256, 256>>>(dt_bias, A_log);
    // 3. depthwise causal conv + SiLU
    conv_kernel<<<((size_t)NBL * CONV_DIM) / 256, 256>>>(conv_w, conv_b);
    // 4a. within-chunk cumprod of dA (warp-parallel prefix product)
    cumP_kernel<<<32, 256>>>();
    // 4b. chunked local scan (pass A)
    scan_kernel<<<dim3(8, NC, 32), 128>>>(D_param);
    // 4c. chunk carry recurrence (pass B)
    passB_kernel<<<(32 * HEADDIM * D_STATE / 4) / 256, 256>>>();
    // 4d. carry fixup of y (pass C)
    fixup_kernel<<<dim3(8, NC - 1, 32), 128>>>();
    // 5. gate + RMSNorm
    mulnorm_kernel<<<NBL, 256>>>(norm_w);
    // 6. out_proj GEMM + residual (f32x2 packed), transposed store
    gemm2_kernel<<<dim3(LSEQ / 128, DIM / 128, BSZ), 256>>>(out_proj_w, x, out);
}

// round 9
// speedup vs baseline: 1.5947x; 1.4752x over previous
#include <cuda_runtime.h>
#include <cuda_bf16.h>
#include <cstdint>

// ---------------- problem constants ----------------
#define BSZ        4
#define DIM        512
#define D_INNER    1024
#define HEADDIM    128
#define NHEADS     8
#define D_STATE    128
#define D_CONV     4
#define CONV_DIM   1280          // D_INNER + 2*D_STATE
#define D_IN_PROJ  2312          // 2*D_INNER + 2*D_STATE + NHEADS
#define LSEQ       4096          // 16*16*16
#define NBL        (BSZ * LSEQ)  // 16384 rows (b,l)
#define NC         8             // scan chunks
#define CHUNK      (LSEQ / NC)   // 512 steps per chunk

// ---------------- device scratch (static globals; no allocation) ----------------
__device__ __align__(128) float  g_zx  [(size_t)NBL * D_IN_PROJ];   // in_proj out (z | xBC | unused dt)
__device__ __align__(128) float  g_conv[(size_t)NBL * CONV_DIM];    // conv+silu out (xs | B | C)
__device__ __align__(128) float2 g_dtdA[NBL * NHEADS];              // (dt, exp(dt*A)) packed
__device__ __align__(128) float  g_y   [(size_t)NBL * D_INNER];     // scan out, normed in-place
__device__ __align__(128) float  g_S   [(size_t)32 * NC * HEADDIM * D_STATE]; // chunk states (16MB)
__device__ __align__(128) float  g_cumP[NBL * NHEADS];              // within-chunk cumprod of dA

// ---------------- helpers ----------------
__device__ __forceinline__ uint64_t pack2(float lo, float hi) {
    uint64_t r; asm("mov.b64 %0, {%1, %2};" : "=l"(r) : "f"(lo), "f"(hi)); return r;
}
__device__ __forceinline__ void unpack2(uint64_t v, float& lo, float& hi) {
    asm("mov.b64 {%0, %1}, %2;" : "=f"(lo), "=f"(hi) : "l"(v));
}
__device__ __forceinline__ uint64_t fma2(uint64_t a, uint64_t b, uint64_t c) {
    uint64_t d; asm("fma.rn.f32x2 %0, %1, %2, %3;" : "=l"(d) : "l"(a), "l"(b), "l"(c)); return d;
}
__device__ __forceinline__ uint64_t mul2(uint64_t a, uint64_t b) {
    uint64_t d; asm("mul.rn.f32x2 %0, %1, %2;" : "=l"(d) : "l"(a), "l"(b)); return d;
}
__device__ __forceinline__ uint32_t f2tf32(float f) {
    uint32_t r; asm("cvt.rna.tf32.f32 %0, %1;" : "=r"(r) : "f"(f)); return r;
}
// Reduce 4 per-thread values over 32 lanes with 6 shuffles.
// Returns: lane j (j = lane & 3) holds full sum of v_j.
__device__ __forceinline__ float reduce4(float v0, float v1, float v2, float v3, int lane) {
    float a = (lane & 1) ? v1 : v0;
    float b = (lane & 1) ? v0 : v1;
    a += __shfl_xor_sync(0xffffffffu, b, 1);
    float c = (lane & 1) ? v3 : v2;
    float d = (lane & 1) ? v2 : v3;
    c += __shfl_xor_sync(0xffffffffu, d, 1);
    float e = (lane & 2) ? c : a;
    float f = (lane & 2) ? a : c;
    e += __shfl_xor_sync(0xffffffffu, f, 2);
    e += __shfl_xor_sync(0xffffffffu, e, 4);
    e += __shfl_xor_sync(0xffffffffu, e, 8);
    e += __shfl_xor_sync(0xffffffffu, e, 16);
    return e;
}

#define MMA_TF32(c, a, b) \
    asm volatile("mma.sync.aligned.m16n8k8.row.col.f32.tf32.tf32.f32 " \
        "{%0,%1,%2,%3}, {%4,%5,%6,%7}, {%8,%9}, {%0,%1,%2,%3};" \
        : "+f"((c)[0]), "+f"((c)[1]), "+f"((c)[2]), "+f"((c)[3]) \
        : "r"((a)[0]), "r"((a)[1]), "r"((a)[2]), "r"((a)[3]), \
          "r"((b)[0]), "r"((b)[1]))

// =====================================================================
// GEMM1 (tf32 tensor core): zxbcdt[m][n] = sum_k x[b][k][l]*W[n][k].
// Covers n in [0, 2304) only (18 full 128-blocks); dt cols via dtprep.
// Block 128x128, kc=16, 8 warps (2x4), warp tile 64x32, m16n8k8 frags.
// =====================================================================
__global__ __launch_bounds__(256) void gemm1_kernel(const float* __restrict__ x,
                                                    const float* __restrict__ W) {
    __shared__ uint32_t As[16][136];   // [k][m], tf32 bits
    __shared__ uint32_t Bs[128][20];   // [n][k], tf32 bits
    const int tid = threadIdx.x;
    const int m0 = blockIdx.y * 128;
    const int n0 = blockIdx.x * 128;
    const int b = m0 >> 12, l0 = m0 & 4095;
    const float* Ap = x + (size_t)b * DIM * LSEQ + l0;
    const float* Bp = W + (size_t)n0 * DIM;

    const int ka = tid >> 4;           // 0..15
    const int ma = (tid & 15) * 8;     // 0..120
    const int nb = tid >> 1;           // 0..127
    const int kb = (tid & 1) * 8;      // 0 or 8

    const int wid = tid >> 5, lane = tid & 31;
    const int wm = (wid >> 2) * 64;    // 0 or 64
    const int wn = (wid & 3) * 32;     // 0..96
    const int gid = lane >> 2, tig = lane & 3;

    float c[4][4][4];
#pragma unroll
    for (int i = 0; i < 4; i++)
#pragma unroll
        for (int j = 0; j < 4; j++)
#pragma unroll
            for (int q = 0; q < 4; q++) c[i][j][q] = 0.f;

    for (int k0 = 0; k0 < DIM; k0 += 16) {
        float4 av0 = *(const float4*)(Ap + (size_t)(k0 + ka) * LSEQ + ma);
        float4 av1 = *(const float4*)(Ap + (size_t)(k0 + ka) * LSEQ + ma + 4);
        float4 bv0 = *(const float4*)(Bp + (size_t)nb * DIM + k0 + kb);
        float4 bv1 = *(const float4*)(Bp + (size_t)nb * DIM + k0 + kb + 4);
        __syncthreads();
        {
            uint4 t;
            t.x = f2tf32(av0.x); t.y = f2tf32(av0.y); t.z = f2tf32(av0.z); t.w = f2tf32(av0.w);
            *(uint4*)&As[ka][ma] = t;
            t.x = f2tf32(av1.x); t.y = f2tf32(av1.y); t.z = f2tf32(av1.z); t.w = f2tf32(av1.w);
            *(uint4*)&As[ka][ma + 4] = t;
            t.x = f2tf32(bv0.x); t.y = f2tf32(bv0.y); t.z = f2tf32(bv0.z); t.w = f2tf32(bv0.w);
            *(uint4*)&Bs[nb][kb] = t;
            t.x = f2tf32(bv1.x); t.y = f2tf32(bv1.y); t.z = f2tf32(bv1.z); t.w = f2tf32(bv1.w);
            *(uint4*)&Bs[nb][kb + 4] = t;
        }
        __syncthreads();
#pragma unroll
        for (int kk = 0; kk < 16; kk += 8) {
            uint32_t af[4][4], bf[4][2];
#pragma unroll
            for (int mi = 0; mi < 4; mi++) {
                const int mr = wm + mi * 16 + gid;
                af[mi][0] = As[kk + tig][mr];
                af[mi][1] = As[kk + tig][mr + 8];
                af[mi][2] = As[kk + tig + 4][mr];
                af[mi][3] = As[kk + tig + 4][mr + 8];
            }
#pragma unroll
            for (int ni = 0; ni < 4; ni++) {
                const int nr = wn + ni * 8 + gid;
                bf[ni][0] = Bs[nr][kk + tig];
                bf[ni][1] = Bs[nr][kk + tig + 4];
            }
#pragma unroll
            for (int mi = 0; mi < 4; mi++)
#pragma unroll
                for (int ni = 0; ni < 4; ni++)
                    MMA_TF32(c[mi][ni], af[mi], bf[ni]);
        }
    }

#pragma unroll
    for (int mi = 0; mi < 4; mi++) {
#pragma unroll
        for (int ni = 0; ni < 4; ni++) {
            const int row = m0 + wm + mi * 16 + gid;
            const int col = n0 + wn + ni * 8 + tig * 2;
            float2 v0; v0.x = c[mi][ni][0]; v0.y = c[mi][ni][1];
            float2 v1; v1.x = c[mi][ni][2]; v1.y = c[mi][ni][3];
            *(float2*)(g_zx + (size_t)row * D_IN_PROJ + col)       = v0;
            *(float2*)(g_zx + (size_t)(row + 8) * D_IN_PROJ + col) = v1;
        }
    }
}

// =====================================================================
// dtprep: exact fp32 dt projection + softplus + dA.
// dt_raw[bl][h] = sum_k x[b][k][l] * W[2304+h][k]; writes g_dtdA.
// =====================================================================
__global__ __launch_bounds__(256) void dtprep_kernel(const float* __restrict__ x,
                                                     const float* __restrict__ W,
                                                     const float* __restrict__ dt_bias,
                                                     const float* __restrict__ A_log) {
    __shared__ float Ws[8][516];       // pad 516 -> conflict-free h-spread
    const int tid = threadIdx.x;
    for (int i = tid; i < 8 * DIM; i += 256)
        Ws[i >> 9][i & 511] = W[(size_t)(D_INNER + CONV_DIM) * DIM + i];
    __syncthreads();

    const int gid = blockIdx.x * 256 + tid;   // < NBL*NHEADS
    const int bl = gid >> 3, h = gid & 7;
    const int b = bl >> 12, l = bl & 4095;
    const float* xp = x + (size_t)b * DIM * LSEQ + l;
    float a0 = 0.f, a1 = 0.f, a2 = 0.f, a3 = 0.f;
#pragma unroll 4
    for (int k = 0; k < DIM; k += 4) {
        a0 = fmaf(xp[(size_t)(k + 0) * LSEQ], Ws[h][k + 0], a0);
        a1 = fmaf(xp[(size_t)(k + 1) * LSEQ], Ws[h][k + 1], a1);
        a2 = fmaf(xp[(size_t)(k + 2) * LSEQ], Ws[h][k + 2], a2);
        a3 = fmaf(xp[(size_t)(k + 3) * LSEQ], Ws[h][k + 3], a3);
    }
    float v = (a0 + a1) + (a2 + a3) + dt_bias[h];
    float dt = (v > 20.f) ? v : log1pf(expf(v));
    float A = -expf(A_log[h]);
    g_dtdA[gid] = make_float2(dt, expf(dt * A));
}

// =====================================================================
// conv: causal depthwise conv over l (width 4) + bias, then SiLU.
// =====================================================================
__global__ __launch_bounds__(256) void conv_kernel(const float* __restrict__ conv_w,
                                                   const float* __restrict__ conv_b) {
    const int gid = blockIdx.x * 256 + threadIdx.x;   // exactly NBL*CONV_DIM
    const int bl = gid / CONV_DIM;
    const int c  = gid - bl * CONV_DIM;
    const int l  = bl & 4095;
    const float w0 = conv_w[c * 4 + 0], w1 = conv_w[c * 4 + 1];
    const float w2 = conv_w[c * 4 + 2], w3 = conv_w[c * 4 + 3];
    const float* base = g_zx + (size_t)bl * D_IN_PROJ + D_INNER + c;
    float acc = conv_b[c];
    if (l >= 3) {
        acc += base[-3 * D_IN_PROJ] * w0;
        acc += base[-2 * D_IN_PROJ] * w1;
        acc += base[-1 * D_IN_PROJ] * w2;
        acc += base[0] * w3;
    } else {
        if (l >= 2) acc += base[-2 * D_IN_PROJ] * w1;
        if (l >= 1) acc += base[-1 * D_IN_PROJ] * w2;
        acc += base[0] * w3;
    }
    g_conv[gid] = acc / (1.f + expf(-acc));
}

// =====================================================================
// cumP: warp-parallel prefix product. 256 chains (b,h,chunk).
// =====================================================================
__global__ __launch_bounds__(256) void cumP_kernel() {
    const int gw   = blockIdx.x * 8 + (threadIdx.x >> 5);   // global warp 0..255
    const int lane = threadIdx.x & 31;
    const int bh = gw >> 3, c = gw & 7;
    const int b = bh >> 3, h = bh & 7;
    const int blbase = b << 12;
    const int tbase = c * CHUNK + lane * 16;

    float vals[16];
    float p = 1.f;
#pragma unroll
    for (int i = 0; i < 16; i++) {
        vals[i] = g_dtdA[(blbase + tbase + i) * NHEADS + h].y;
        p *= vals[i];
    }
    float scan = p;
#pragma unroll
    for (int off = 1; off < 32; off <<= 1) {
        float v = __shfl_up_sync(0xffffffffu, scan, off);
        if (lane >= off) scan *= v;
    }
    float excl = __shfl_up_sync(0xffffffffu, scan, 1);
    if (lane == 0) excl = 1.f;

    float run = excl;
#pragma unroll
    for (int i = 0; i < 16; i++) {
        run *= vals[i];
        g_cumP[(blbase + tbase + i) * NHEADS + h] = run;
    }
}

// =====================================================================
// scan pass A: chunked local scan. Grid (pt:8, c:8, bh:32) = 2048 blocks.
// =====================================================================
#define SCAN_LD(buf, t) do {                                                  \
    const float* _br = Bp + (size_t)(t) * CONV_DIM;                           \
    B##buf = *(const ulonglong2*)_br;                                         \
    C##buf = *(const ulonglong2*)(_br + D_STATE);                             \
    x##buf = *(const float4*)(Xp + (size_t)(t) * CONV_DIM);                   \
    dd##buf = DDp[(t) * NHEADS];                                              \
} while (0)

#define SCAN_P(buf, p, xi, vout) do {                                         \
    const float _dtx = (xi) * dd##buf.x;                                      \
    const uint64_t _dtx2 = pack2(_dtx, _dtx);                                 \
    s##p##0 = fma2(B##buf.x, _dtx2, mul2(s##p##0, _dA2));                     \
    s##p##1 = fma2(B##buf.y, _dtx2, mul2(s##p##1, _dA2));                     \
    uint64_t _y2 = fma2(s##p##1, C##buf.y, mul2(s##p##0, C##buf.x));          \
    float _lo, _hi; unpack2(_y2, _lo, _hi);                                   \
    vout = _lo + _hi;                                                         \
} while (0)

#define SCAN_STEP(buf, t) do {                                                \
    const uint64_t _dA2 = pack2(dd##buf.y, dd##buf.y);                        \
    float v0, v1, v2, v3;                                                     \
    SCAN_P(buf, 0, x##buf.x, v0);                                             \
    SCAN_P(buf, 1, x##buf.y, v1);                                             \
    SCAN_P(buf, 2, x##buf.z, v2);                                             \
    SCAN_P(buf, 3, x##buf.w, v3);                                             \
    float _e = reduce4(v0, v1, v2, v3, lane);                                 \
    if (lane < 4) {                                                           \
        float _xs = (lane == 0) ? x##buf.x : (lane == 1) ? x##buf.y           \
                  : (lane == 2) ? x##buf.z : x##buf.w;                        \
        Yp[(size_t)(t) * D_INNER + lane] = _e + Dh * _xs;                     \
    }                                                                         \
} while (0)

__global__ __launch_bounds__(128, 5) void scan_kernel(const float* __restrict__ D_param) {
    const int tid  = threadIdx.x;
    const int lane = tid & 31;
    const int w    = tid >> 5;          // 0..3
    const int pt = blockIdx.x;          // 0..7
    const int c  = blockIdx.y;          // 0..7
    const int bh = blockIdx.z;          // 0..31
    const int b = bh >> 3, h = bh & 7;
    const int p0 = pt * 16 + w * 4;
    const int n0 = lane * 4;
    const float Dh = D_param[h];
    const int blbase = b << 12;
    const int t0 = c * CHUNK, tend = t0 + CHUNK;

    const float* Bp = g_conv + (size_t)blbase * CONV_DIM + D_INNER + n0;
    const float* Xp = g_conv + (size_t)blbase * CONV_DIM + h * HEADDIM + p0;
    const float2* DDp = g_dtdA + blbase * NHEADS + h;
    float* Yp = g_y + (size_t)blbase * D_INNER + h * HEADDIM + p0;

    uint64_t s00 = 0, s01 = 0, s10 = 0, s11 = 0;
    uint64_t s20 = 0, s21 = 0, s30 = 0, s31 = 0;

    ulonglong2 B0, C0, B1, C1, B2, C2, B3, C3;
    float4 x0, x1, x2, x3;
    float2 dd0, dd1, dd2, dd3;

    SCAN_LD(0, t0);
    SCAN_LD(1, t0 + 1);
    SCAN_LD(2, t0 + 2);
    SCAN_LD(3, t0 + 3);
    for (int t = t0; t < tend; t += 4) {
        SCAN_STEP(0, t);
        SCAN_LD(0, min(t + 4, tend - 1));
        SCAN_STEP(1, t + 1);
        SCAN_LD(1, min(t + 5, tend - 1));
        SCAN_STEP(2, t + 2);
        SCAN_LD(2, min(t + 6, tend - 1));
        SCAN_STEP(3, t + 3);
        SCAN_LD(3, min(t + 7, tend - 1));
    }

    float* sp = g_S + ((size_t)(bh * NC + c) * HEADDIM + p0) * D_STATE + n0;
    { ulonglong2 r; r.x = s00; r.y = s01; *(ulonglong2*)(sp)               = r; }
    { ulonglong2 r; r.x = s10; r.y = s11; *(ulonglong2*)(sp + D_STATE)     = r; }
    { ulonglong2 r; r.x = s20; r.y = s21; *(ulonglong2*)(sp + 2 * D_STATE) = r; }
    { ulonglong2 r; r.x = s30; r.y = s31; *(ulonglong2*)(sp + 3 * D_STATE) = r; }
}

// =====================================================================
// pass B: chunk carry recurrence.
// =====================================================================
__global__ __launch_bounds__(256) void passB_kernel() {
    const int gid = blockIdx.x * 256 + threadIdx.x;
    const int n0 = (gid & 31) * 4;
    const int p  = (gid >> 5) & 127;
    const int bh = gid >> 12;
    const int b = bh >> 3, h = bh & 7;
    const int blbase = b << 12;
    float4 carry = make_float4(0.f, 0.f, 0.f, 0.f);
#pragma unroll
    for (int c = 0; c < NC; c++) {
        float* sp = g_S + ((size_t)(bh * NC + c) * HEADDIM + p) * D_STATE + n0;
        float4 SL = *(float4*)sp;
        *(float4*)sp = carry;
        float Pt = g_cumP[(blbase + c * CHUNK + CHUNK - 1) * NHEADS + h];
        carry.x = SL.x + Pt * carry.x;
        carry.y = SL.y + Pt * carry.y;
        carry.z = SL.z + Pt * carry.z;
        carry.w = SL.w + Pt * carry.w;
    }
}

// =====================================================================
// pass C (fixup): y_t += cumP_t * (C_t · S_in_c). Chunks 1..7 only.
// =====================================================================
__global__ __launch_bounds__(128) void fixup_kernel() {
    const int tid = threadIdx.x, lane = tid & 31, w = tid >> 5;
    const int pt = blockIdx.x;
    const int c  = blockIdx.y + 1;      // 1..7
    const int bh = blockIdx.z;
    const int b = bh >> 3, h = bh & 7;
    const int p0 = pt * 16 + w * 4, n0 = lane * 4;
    const int blbase = b << 12;
    const int t0 = c * CHUNK;

    uint64_t S00, S01, S10, S11, S20, S21, S30, S31;
    {
        const float* sp = g_S + ((size_t)(bh * NC + c) * HEADDIM + p0) * D_STATE + n0;
        ulonglong2 r0 = *(const ulonglong2*)(sp);
        ulonglong2 r1 = *(const ulonglong2*)(sp + D_STATE);
        ulonglong2 r2 = *(const ulonglong2*)(sp + 2 * D_STATE);
        ulonglong2 r3 = *(const ulonglong2*)(sp + 3 * D_STATE);
        S00 = r0.x; S01 = r0.y; S10 = r1.x; S11 = r1.y;
        S20 = r2.x; S21 = r2.y; S30 = r3.x; S31 = r3.y;
    }
    const float* Cp = g_conv + (size_t)blbase * CONV_DIM + D_INNER + D_STATE + n0;
    const float* Pp = g_cumP + blbase * NHEADS + h;
    float* Yp = g_y + (size_t)blbase * D_INNER + h * HEADDIM + p0;

#pragma unroll 2
    for (int t = t0; t < t0 + CHUNK; t++) {
        ulonglong2 Cv = *(const ulonglong2*)(Cp + (size_t)t * CONV_DIM);
        float cp = Pp[t * NHEADS];
        float v0, v1, v2, v3;
        { uint64_t u = fma2(S01, Cv.y, mul2(S00, Cv.x)); float lo, hi; unpack2(u, lo, hi); v0 = lo + hi; }
        { uint64_t u = fma2(S11, Cv.y, mul2(S10, Cv.x)); float lo, hi; unpack2(u, lo, hi); v1 = lo + hi; }
        { uint64_t u = fma2(S21, Cv.y, mul2(S20, Cv.x)); float lo, hi; unpack2(u, lo, hi); v2 = lo + hi; }
        { uint64_t u = fma2(S31, Cv.y, mul2(S30, Cv.x)); float lo, hi; unpack2(u, lo, hi); v3 = lo + hi; }
        float e = reduce4(v0, v1, v2, v3, lane);
        if (lane < 4) {
            float* yp = Yp + (size_t)t * D_INNER + lane;
            *yp += cp * e;
        }
    }
}

// =====================================================================
// mulnorm: y = y * silu(z); y = y * rsqrt(mean(y^2)+1e-5) * norm_w
// =====================================================================
__global__ __launch_bounds__(256) void mulnorm_kernel(const float* __restrict__ norm_w) {
    __shared__ float red[8];
    __shared__ float rinv;
    const int bl = blockIdx.x, tid = threadIdx.x;
    const int lane = tid & 31, w = tid >> 5;
    float4 yv = *(const float4*)(g_y + (size_t)bl * D_INNER + tid * 4);
    float4 zv = *(const float4*)(g_zx + (size_t)bl * D_IN_PROJ + tid * 4);
    float4 t;
    t.x = yv.x * (zv.x / (1.f + expf(-zv.x)));
    t.y = yv.y * (zv.y / (1.f + expf(-zv.y)));
    t.z = yv.z * (zv.z / (1.f + expf(-zv.z)));
    t.w = yv.w * (zv.w / (1.f + expf(-zv.w)));
    float ss = t.x * t.x + t.y * t.y + t.z * t.z + t.w * t.w;
#pragma unroll
    for (int off = 16; off > 0; off >>= 1) ss += __shfl_xor_sync(0xffffffffu, ss, off);
    if (lane == 0) red[w] = ss;
    __syncthreads();
    if (tid == 0) {
        float tot = 0.f;
#pragma unroll
        for (int i = 0; i < 8; i++) tot += red[i];
        rinv = rsqrtf(tot * (1.f / (float)D_INNER) + 1e-5f);
    }
    __syncthreads();
    const float r = rinv;
    float4 w4 = *(const float4*)(norm_w + tid * 4);
    t.x *= r * w4.x; t.y *= r * w4.y; t.z *= r * w4.z; t.w *= r * w4.w;
    *(float4*)(g_y + (size_t)bl * D_INNER + tid * 4) = t;
}

// =====================================================================
// GEMM2 (tf32 tensor core): out[b][d][l] = sum_e Wo[d][e]*y[bl][e] + x.
// Block 128(d) x 128(l), kc=16. A=Wo row-major, B=y (e contiguous).
// =====================================================================
__global__ __launch_bounds__(256) void gemm2_kernel(const float* __restrict__ Wo,
                                                    const float* __restrict__ x,
                                                    float* __restrict__ out) {
    __shared__ uint32_t As[128][20];   // [d][k]
    __shared__ uint32_t Bs[128][20];   // [l][k]
    const int tid = threadIdx.x;
    const int l0 = blockIdx.x * 128;
    const int d0 = blockIdx.y * 128;
    const int b  = blockIdx.z;
    const float* yp = g_y + (size_t)(b * LSEQ + l0) * D_INNER;

    const int rb = tid >> 1;           // 0..127
    const int kb = (tid & 1) * 8;      // 0 or 8

    const int wid = tid >> 5, lane = tid & 31;
    const int wm = (wid >> 2) * 64;
    const int wn = (wid & 3) * 32;
    const int gid = lane >> 2, tig = lane & 3;

    float c[4][4][4];
#pragma unroll
    for (int i = 0; i < 4; i++)
#pragma unroll
        for (int j = 0; j < 4; j++)
#pragma unroll
            for (int q = 0; q < 4; q++) c[i][j][q] = 0.f;

    for (int k0 = 0; k0 < D_INNER; k0 += 16) {
        float4 av0 = *(const float4*)(Wo + (size_t)(d0 + rb) * D_INNER + k0 + kb);
        float4 av1 = *(const float4*)(Wo + (size_t)(d0 + rb) * D_INNER + k0 + kb + 4);
        float4 bv0 = *(const float4*)(yp + (size_t)rb * D_INNER + k0 + kb);
        float4 bv1 = *(const float4*)(yp + (size_t)rb * D_INNER + k0 + kb + 4);
        __syncthreads();
        {
            uint4 t;
            t.x = f2tf32(av0.x); t.y = f2tf32(av0.y); t.z = f2tf32(av0.z); t.w = f2tf32(av0.w);
            *(uint4*)&As[rb][kb] = t;
            t.x = f2tf32(av1.x); t.y = f2tf32(av1.y); t.z = f2tf32(av1.z); t.w = f2tf32(av1.w);
            *(uint4*)&As[rb][kb + 4] = t;
            t.x = f2tf32(bv0.x); t.y = f2tf32(bv0.y); t.z = f2tf32(bv0.z); t.w = f2tf32(bv0.w);
            *(uint4*)&Bs[rb][kb] = t;
            t.x = f2tf32(bv1.x); t.y = f2tf32(bv1.y); t.z = f2tf32(bv1.z); t.w = f2tf32(bv1.w);
            *(uint4*)&Bs[rb][kb + 4] = t;
        }
        __syncthreads();
#pragma unroll
        for (int kk = 0; kk < 16; kk += 8) {
            uint32_t af[4][4], bf[4][2];
#pragma unroll
            for (int mi = 0; mi < 4; mi++) {
                const int mr = wm + mi * 16 + gid;
                af[mi][0] = As[mr][kk + tig];
                af[mi][1] = As[mr + 8][kk + tig];
                af[mi][2] = As[mr][kk + tig + 4];
                af[mi][3] = As[mr + 8][kk + tig + 4];
            }
#pragma unroll
            for (int ni = 0; ni < 4; ni++) {
                const int nr = wn + ni * 8 + gid;
                bf[ni][0] = Bs[nr][kk + tig];
                bf[ni][1] = Bs[nr][kk + tig + 4];
            }
#pragma unroll
            for (int mi = 0; mi < 4; mi++)
#pragma unroll
                for (int ni = 0; ni < 4; ni++)
                    MMA_TF32(c[mi][ni], af[mi], bf[ni]);
        }
    }

    const size_t base = (size_t)b * DIM * LSEQ;
#pragma unroll
    for (int mi = 0; mi < 4; mi++) {
#pragma unroll
        for (int ni = 0; ni < 4; ni++) {
            const int d = d0 + wm + mi * 16 + gid;
            const int l = l0 + wn + ni * 8 + tig * 2;
            const size_t off0 = base + (size_t)d * LSEQ + l;
            const size_t off1 = off0 + (size_t)8 * LSEQ;
            float2 x0 = *(const float2*)(x + off0);
            float2 x1 = *(const float2*)(x + off1);
            float2 o0; o0.x = c[mi][ni][0] + x0.x; o0.y = c[mi][ni][1] + x0.y;
            float2 o1; o1.x = c[mi][ni][2] + x1.x; o1.y = c[mi][ni][3] + x1.y;
            *(float2*)(out + off0) = o0;
            *(float2*)(out + off1) = o1;
        }
    }
}

// =====================================================================
extern "C" void kernel_launch(void* const* d_in, const int* in_sizes, int n_in,
                              void* d_out, int out_size) {
    const float* x          = (const float*)d_in[0];
    const float* in_proj_w  = (const float*)d_in[1];
    const float* conv_w     = (const float*)d_in[2];
    const float* conv_b     = (const float*)d_in[3];
    const float* dt_bias    = (const float*)d_in[4];
    const float* A_log      = (const float*)d_in[5];
    const float* D_param    = (const float*)d_in[6];
    const float* norm_w     = (const float*)d_in[7];
    const float* out_proj_w = (const float*)d_in[8];
    float* out = (float*)d_out;

    // 1. in_proj GEMM, tf32 tensor cores (cols 0..2303; dt cols separate)
    gemm1_kernel<<<dim3(18, NBL / 128), 256>>>(x, in_proj_w);
    // 2. exact fp32 dt projection + softplus + dA
    dtprep_kernel<<<(NBL * NHEADS) / 256, 256>>>(x, in_proj_w, dt_bias, A_log);
    // 3. depthwise causal conv + SiLU
    conv_kernel<<<((size_t)NBL * CONV_DIM) / 256, 256>>>(conv_w, conv_b);
    // 4a. within-chunk cumprod of dA
    cumP_kernel<<<32, 256>>>();
    // 4b. chunked local scan (pass A)
    scan_kernel<<<dim3(8, NC, 32), 128>>>(D_param);
    // 4c. chunk carry recurrence (pass B)
    passB_kernel<<<(32 * HEADDIM * D_STATE / 4) / 256, 256>>>();
    // 4d. carry fixup of y (pass C)
    fixup_kernel<<<dim3(8, NC - 1, 32), 128>>>();
    // 5. gate + RMSNorm
    mulnorm_kernel<<<NBL, 256>>>(norm_w);
    // 6. out_proj GEMM, tf32 tensor cores + residual, transposed store
    gemm2_kernel<<<dim3(LSEQ / 128, DIM / 128, BSZ), 256>>>(out_proj_w, x, out);
}

// round 10
// speedup vs baseline: 1.6777x; 1.0521x over previous
#include <cuda_runtime.h>
#include <cuda_bf16.h>
#include <cstdint>

// ---------------- problem constants ----------------
#define BSZ        4
#define DIM        512
#define D_INNER    1024
#define HEADDIM    128
#define NHEADS     8
#define D_STATE    128
#define D_CONV     4
#define CONV_DIM   1280          // D_INNER + 2*D_STATE
#define D_IN_PROJ  2312          // 2*D_INNER + 2*D_STATE + NHEADS
#define LSEQ       4096          // 16*16*16
#define NBL        (BSZ * LSEQ)  // 16384 rows (b,l)
#define NC         8             // scan chunks
#define CHUNK      (LSEQ / NC)   // 512 steps per chunk

// ---------------- device scratch (static globals; no allocation) ----------------
__device__ __align__(128) float  g_zx  [(size_t)NBL * D_IN_PROJ];   // in_proj out (z | xBC | unused dt)
__device__ __align__(128) float  g_conv[(size_t)NBL * CONV_DIM];    // conv+silu out (xs | B | C)
__device__ __align__(128) float2 g_dtdA[NBL * NHEADS];              // (dt, exp(dt*A)) packed
__device__ __align__(128) float  g_y   [(size_t)NBL * D_INNER];     // scan out, normed in-place
__device__ __align__(128) float  g_S   [(size_t)32 * NC * HEADDIM * D_STATE]; // chunk states (16MB)
__device__ __align__(128) float  g_cumP[NBL * NHEADS];              // within-chunk cumprod of dA

// ---------------- helpers ----------------
__device__ __forceinline__ uint64_t pack2(float lo, float hi) {
    uint64_t r; asm("mov.b64 %0, {%1, %2};" : "=l"(r) : "f"(lo), "f"(hi)); return r;
}
__device__ __forceinline__ void unpack2(uint64_t v, float& lo, float& hi) {
    asm("mov.b64 {%0, %1}, %2;" : "=f"(lo), "=f"(hi) : "l"(v));
}
__device__ __forceinline__ uint64_t fma2(uint64_t a, uint64_t b, uint64_t c) {
    uint64_t d; asm("fma.rn.f32x2 %0, %1, %2, %3;" : "=l"(d) : "l"(a), "l"(b), "l"(c)); return d;
}
__device__ __forceinline__ uint64_t mul2(uint64_t a, uint64_t b) {
    uint64_t d; asm("mul.rn.f32x2 %0, %1, %2;" : "=l"(d) : "l"(a), "l"(b)); return d;
}
__device__ __forceinline__ uint32_t f2tf32(float f) {
    uint32_t r; asm("cvt.rna.tf32.f32 %0, %1;" : "=r"(r) : "f"(f)); return r;
}
// Reduce 4 per-thread values over 32 lanes with 6 shuffles.
// Returns: lane j (j = lane & 3) holds full sum of v_j.
__device__ __forceinline__ float reduce4(float v0, float v1, float v2, float v3, int lane) {
    float a = (lane & 1) ? v1 : v0;
    float b = (lane & 1) ? v0 : v1;
    a += __shfl_xor_sync(0xffffffffu, b, 1);
    float c = (lane & 1) ? v3 : v2;
    float d = (lane & 1) ? v2 : v3;
    c += __shfl_xor_sync(0xffffffffu, d, 1);
    float e = (lane & 2) ? c : a;
    float f = (lane & 2) ? a : c;
    e += __shfl_xor_sync(0xffffffffu, f, 2);
    e += __shfl_xor_sync(0xffffffffu, e, 4);
    e += __shfl_xor_sync(0xffffffffu, e, 8);
    e += __shfl_xor_sync(0xffffffffu, e, 16);
    return e;
}
// Reduce 8 per-thread values over 32 lanes with 9 shuffles.
// Returns: lane L holds full sum of v[L & 7].
__device__ __forceinline__ float reduce8(const float* v, int lane) {
    float A  = (lane & 1) ? v[1] : v[0];
    float As = (lane & 1) ? v[0] : v[1];
    A += __shfl_xor_sync(0xffffffffu, As, 1);
    float B  = (lane & 1) ? v[3] : v[2];
    float Bs = (lane & 1) ? v[2] : v[3];
    B += __shfl_xor_sync(0xffffffffu, Bs, 1);
    float C  = (lane & 1) ? v[5] : v[4];
    float Cs = (lane & 1) ? v[4] : v[5];
    C += __shfl_xor_sync(0xffffffffu, Cs, 1);
    float D  = (lane & 1) ? v[7] : v[6];
    float Ds = (lane & 1) ? v[6] : v[7];
    D += __shfl_xor_sync(0xffffffffu, Ds, 1);
    float E  = (lane & 2) ? B : A;
    float Es = (lane & 2) ? A : B;
    E += __shfl_xor_sync(0xffffffffu, Es, 2);
    float F  = (lane & 2) ? D : C;
    float Fs = (lane & 2) ? C : D;
    F += __shfl_xor_sync(0xffffffffu, Fs, 2);
    float G  = (lane & 4) ? F : E;
    float Gs = (lane & 4) ? E : F;
    G += __shfl_xor_sync(0xffffffffu, Gs, 4);
    G += __shfl_xor_sync(0xffffffffu, G, 8);
    G += __shfl_xor_sync(0xffffffffu, G, 16);
    return G;
}

#define MMA_TF32(c, a, b) \
    asm volatile("mma.sync.aligned.m16n8k8.row.col.f32.tf32.tf32.f32 " \
        "{%0,%1,%2,%3}, {%4,%5,%6,%7}, {%8,%9}, {%0,%1,%2,%3};" \
        : "+f"((c)[0]), "+f"((c)[1]), "+f"((c)[2]), "+f"((c)[3]) \
        : "r"((a)[0]), "r"((a)[1]), "r"((a)[2]), "r"((a)[3]), \
          "r"((b)[0]), "r"((b)[1]))

// =====================================================================
// GEMM1 (tf32 tensor core): zxbcdt[m][n] = sum_k x[b][k][l]*W[n][k].
// Covers n in [0, 2304) only; dt cols via dtprep.
// =====================================================================
__global__ __launch_bounds__(256) void gemm1_kernel(const float* __restrict__ x,
                                                    const float* __restrict__ W) {
    __shared__ uint32_t As[16][136];   // [k][m], tf32 bits
    __shared__ uint32_t Bs[128][20];   // [n][k], tf32 bits
    const int tid = threadIdx.x;
    const int m0 = blockIdx.y * 128;
    const int n0 = blockIdx.x * 128;
    const int b = m0 >> 12, l0 = m0 & 4095;
    const float* Ap = x + (size_t)b * DIM * LSEQ + l0;
    const float* Bp = W + (size_t)n0 * DIM;

    const int ka = tid >> 4;           // 0..15
    const int ma = (tid & 15) * 8;     // 0..120
    const int nb = tid >> 1;           // 0..127
    const int kb = (tid & 1) * 8;      // 0 or 8

    const int wid = tid >> 5, lane = tid & 31;
    const int wm = (wid >> 2) * 64;    // 0 or 64
    const int wn = (wid & 3) * 32;     // 0..96
    const int gid = lane >> 2, tig = lane & 3;

    float c[4][4][4];
#pragma unroll
    for (int i = 0; i < 4; i++)
#pragma unroll
        for (int j = 0; j < 4; j++)
#pragma unroll
            for (int q = 0; q < 4; q++) c[i][j][q] = 0.f;

    for (int k0 = 0; k0 < DIM; k0 += 16) {
        float4 av0 = *(const float4*)(Ap + (size_t)(k0 + ka) * LSEQ + ma);
        float4 av1 = *(const float4*)(Ap + (size_t)(k0 + ka) * LSEQ + ma + 4);
        float4 bv0 = *(const float4*)(Bp + (size_t)nb * DIM + k0 + kb);
        float4 bv1 = *(const float4*)(Bp + (size_t)nb * DIM + k0 + kb + 4);
        __syncthreads();
        {
            uint4 t;
            t.x = f2tf32(av0.x); t.y = f2tf32(av0.y); t.z = f2tf32(av0.z); t.w = f2tf32(av0.w);
            *(uint4*)&As[ka][ma] = t;
            t.x = f2tf32(av1.x); t.y = f2tf32(av1.y); t.z = f2tf32(av1.z); t.w = f2tf32(av1.w);
            *(uint4*)&As[ka][ma + 4] = t;
            t.x = f2tf32(bv0.x); t.y = f2tf32(bv0.y); t.z = f2tf32(bv0.z); t.w = f2tf32(bv0.w);
            *(uint4*)&Bs[nb][kb] = t;
            t.x = f2tf32(bv1.x); t.y = f2tf32(bv1.y); t.z = f2tf32(bv1.z); t.w = f2tf32(bv1.w);
            *(uint4*)&Bs[nb][kb + 4] = t;
        }
        __syncthreads();
#pragma unroll
        for (int kk = 0; kk < 16; kk += 8) {
            uint32_t af[4][4], bf[4][2];
#pragma unroll
            for (int mi = 0; mi < 4; mi++) {
                const int mr = wm + mi * 16 + gid;
                af[mi][0] = As[kk + tig][mr];
                af[mi][1] = As[kk + tig][mr + 8];
                af[mi][2] = As[kk + tig + 4][mr];
                af[mi][3] = As[kk + tig + 4][mr + 8];
            }
#pragma unroll
            for (int ni = 0; ni < 4; ni++) {
                const int nr = wn + ni * 8 + gid;
                bf[ni][0] = Bs[nr][kk + tig];
                bf[ni][1] = Bs[nr][kk + tig + 4];
            }
#pragma unroll
            for (int mi = 0; mi < 4; mi++)
#pragma unroll
                for (int ni = 0; ni < 4; ni++)
                    MMA_TF32(c[mi][ni], af[mi], bf[ni]);
        }
    }

#pragma unroll
    for (int mi = 0; mi < 4; mi++) {
#pragma unroll
        for (int ni = 0; ni < 4; ni++) {
            const int row = m0 + wm + mi * 16 + gid;
            const int col = n0 + wn + ni * 8 + tig * 2;
            float2 v0; v0.x = c[mi][ni][0]; v0.y = c[mi][ni][1];
            float2 v1; v1.x = c[mi][ni][2]; v1.y = c[mi][ni][3];
            *(float2*)(g_zx + (size_t)row * D_IN_PROJ + col)       = v0;
            *(float2*)(g_zx + (size_t)(row + 8) * D_IN_PROJ + col) = v1;
        }
    }
}

// =====================================================================
// dtprep: exact fp32 dt projection + softplus + dA.
// =====================================================================
__global__ __launch_bounds__(256) void dtprep_kernel(const float* __restrict__ x,
                                                     const float* __restrict__ W,
                                                     const float* __restrict__ dt_bias,
                                                     const float* __restrict__ A_log) {
    __shared__ float Ws[8][516];
    const int tid = threadIdx.x;
    for (int i = tid; i < 8 * DIM; i += 256)
        Ws[i >> 9][i & 511] = W[(size_t)(D_INNER + CONV_DIM) * DIM + i];
    __syncthreads();

    const int gid = blockIdx.x * 256 + tid;   // < NBL*NHEADS
    const int bl = gid >> 3, h = gid & 7;
    const int b = bl >> 12, l = bl & 4095;
    const float* xp = x + (size_t)b * DIM * LSEQ + l;
    float a0 = 0.f, a1 = 0.f, a2 = 0.f, a3 = 0.f;
#pragma unroll 4
    for (int k = 0; k < DIM; k += 4) {
        a0 = fmaf(xp[(size_t)(k + 0) * LSEQ], Ws[h][k + 0], a0);
        a1 = fmaf(xp[(size_t)(k + 1) * LSEQ], Ws[h][k + 1], a1);
        a2 = fmaf(xp[(size_t)(k + 2) * LSEQ], Ws[h][k + 2], a2);
        a3 = fmaf(xp[(size_t)(k + 3) * LSEQ], Ws[h][k + 3], a3);
    }
    float v = (a0 + a1) + (a2 + a3) + dt_bias[h];
    float dt = (v > 20.f) ? v : log1pf(expf(v));
    float A = -expf(A_log[h]);
    g_dtdA[gid] = make_float2(dt, expf(dt * A));
}

// =====================================================================
// conv: causal depthwise conv over l (width 4) + bias, then SiLU.
// =====================================================================
__global__ __launch_bounds__(256) void conv_kernel(const float* __restrict__ conv_w,
                                                   const float* __restrict__ conv_b) {
    const int gid = blockIdx.x * 256 + threadIdx.x;   // exactly NBL*CONV_DIM
    const int bl = gid / CONV_DIM;
    const int c  = gid - bl * CONV_DIM;
    const int l  = bl & 4095;
    const float w0 = conv_w[c * 4 + 0], w1 = conv_w[c * 4 + 1];
    const float w2 = conv_w[c * 4 + 2], w3 = conv_w[c * 4 + 3];
    const float* base = g_zx + (size_t)bl * D_IN_PROJ + D_INNER + c;
    float acc = conv_b[c];
    if (l >= 3) {
        acc += base[-3 * D_IN_PROJ] * w0;
        acc += base[-2 * D_IN_PROJ] * w1;
        acc += base[-1 * D_IN_PROJ] * w2;
        acc += base[0] * w3;
    } else {
        if (l >= 2) acc += base[-2 * D_IN_PROJ] * w1;
        if (l >= 1) acc += base[-1 * D_IN_PROJ] * w2;
        acc += base[0] * w3;
    }
    g_conv[gid] = acc / (1.f + expf(-acc));
}

// =====================================================================
// cumP: warp-parallel prefix product. 256 chains (b,h,chunk).
// =====================================================================
__global__ __launch_bounds__(256) void cumP_kernel() {
    const int gw   = blockIdx.x * 8 + (threadIdx.x >> 5);
    const int lane = threadIdx.x & 31;
    const int bh = gw >> 3, c = gw & 7;
    const int b = bh >> 3, h = bh & 7;
    const int blbase = b << 12;
    const int tbase = c * CHUNK + lane * 16;

    float vals[16];
    float p = 1.f;
#pragma unroll
    for (int i = 0; i < 16; i++) {
        vals[i] = g_dtdA[(blbase + tbase + i) * NHEADS + h].y;
        p *= vals[i];
    }
    float scan = p;
#pragma unroll
    for (int off = 1; off < 32; off <<= 1) {
        float v = __shfl_up_sync(0xffffffffu, scan, off);
        if (lane >= off) scan *= v;
    }
    float excl = __shfl_up_sync(0xffffffffu, scan, 1);
    if (lane == 0) excl = 1.f;

    float run = excl;
#pragma unroll
    for (int i = 0; i < 16; i++) {
        run *= vals[i];
        g_cumP[(blbase + tbase + i) * NHEADS + h] = run;
    }
}

// =====================================================================
// scan pass A v2: 8 p-rows per warp. Grid (pt:4, c:8, bh:32) = 1024
// blocks, 128 threads = 4 warps; warp w owns p [pt*32+8w, +8); lane owns
// n-slice [lane*4, +4): states = 8 x 2 packed f32x2. Depth-2 prefetch.
// B/C/dtdA load cost per p-row is HALF of the 4p layout.
// =====================================================================
struct ScanBuf {
    ulonglong2 B, C;
    float4 xa, xb;
    float2 dd;
};

__device__ __forceinline__ void scan_load(ScanBuf& s, int t,
                                          const float* Bp, const float* Xp,
                                          const float2* DDp) {
    const float* br = Bp + (size_t)t * CONV_DIM;
    s.B  = *(const ulonglong2*)br;
    s.C  = *(const ulonglong2*)(br + D_STATE);
    s.xa = *(const float4*)(Xp + (size_t)t * CONV_DIM);
    s.xb = *(const float4*)(Xp + (size_t)t * CONV_DIM + 4);
    s.dd = DDp[t * NHEADS];
}

__device__ __forceinline__ void scan_step(const ScanBuf& bf, int t,
                                          uint64_t s[8][2], float* Yp,
                                          float Dh, int lane) {
    const uint64_t dA2 = pack2(bf.dd.y, bf.dd.y);
    const float xv[8] = { bf.xa.x, bf.xa.y, bf.xa.z, bf.xa.w,
                          bf.xb.x, bf.xb.y, bf.xb.z, bf.xb.w };
    float v[8];
#pragma unroll
    for (int i = 0; i < 8; i++) {
        const float dtx = xv[i] * bf.dd.x;
        const uint64_t dtx2 = pack2(dtx, dtx);
        s[i][0] = fma2(bf.B.x, dtx2, mul2(s[i][0], dA2));
        s[i][1] = fma2(bf.B.y, dtx2, mul2(s[i][1], dA2));
        uint64_t y2 = fma2(s[i][1], bf.C.y, mul2(s[i][0], bf.C.x));
        float lo, hi; unpack2(y2, lo, hi);
        v[i] = lo + hi;
    }
    float G = reduce8(v, lane);
    if (lane < 8) {
        float xs = (lane & 4) ? ((lane & 2) ? ((lane & 1) ? bf.xb.w : bf.xb.z)
                                            : ((lane & 1) ? bf.xb.y : bf.xb.x))
                              : ((lane & 2) ? ((lane & 1) ? bf.xa.w : bf.xa.z)
                                            : ((lane & 1) ? bf.xa.y : bf.xa.x));
        Yp[(size_t)t * D_INNER + lane] = G + Dh * xs;
    }
}

__global__ __launch_bounds__(128, 5) void scan_kernel(const float* __restrict__ D_param) {
    const int tid  = threadIdx.x;
    const int lane = tid & 31;
    const int w    = tid >> 5;          // 0..3
    const int pt = blockIdx.x;          // 0..3
    const int c  = blockIdx.y;          // 0..7
    const int bh = blockIdx.z;          // 0..31
    const int b = bh >> 3, h = bh & 7;
    const int p0 = pt * 32 + w * 8;     // 8 consecutive p rows per warp
    const int n0 = lane * 4;
    const float Dh = D_param[h];
    const int blbase = b << 12;
    const int t0 = c * CHUNK, tend = t0 + CHUNK;

    const float* Bp = g_conv + (size_t)blbase * CONV_DIM + D_INNER + n0;
    const float* Xp = g_conv + (size_t)blbase * CONV_DIM + h * HEADDIM + p0;
    const float2* DDp = g_dtdA + blbase * NHEADS + h;
    float* Yp = g_y + (size_t)blbase * D_INNER + h * HEADDIM + p0;

    uint64_t s[8][2];
#pragma unroll
    for (int i = 0; i < 8; i++) { s[i][0] = 0; s[i][1] = 0; }

    ScanBuf b0, b1;
    scan_load(b0, t0, Bp, Xp, DDp);
    scan_load(b1, t0 + 1, Bp, Xp, DDp);
    for (int t = t0; t < tend; t += 2) {
        scan_step(b0, t, s, Yp, Dh, lane);
        scan_load(b0, min(t + 2, tend - 1), Bp, Xp, DDp);
        scan_step(b1, t + 1, s, Yp, Dh, lane);
        scan_load(b1, min(t + 3, tend - 1), Bp, Xp, DDp);
    }

    // store final local chunk state: thread covers 8p x 4n
    float* sp = g_S + ((size_t)(bh * NC + c) * HEADDIM + p0) * D_STATE + n0;
#pragma unroll
    for (int i = 0; i < 8; i++) {
        ulonglong2 r; r.x = s[i][0]; r.y = s[i][1];
        *(ulonglong2*)(sp + (size_t)i * D_STATE) = r;
    }
}

// =====================================================================
// pass B: chunk carry recurrence.
// =====================================================================
__global__ __launch_bounds__(256) void passB_kernel() {
    const int gid = blockIdx.x * 256 + threadIdx.x;
    const int n0 = (gid & 31) * 4;
    const int p  = (gid >> 5) & 127;
    const int bh = gid >> 12;
    const int b = bh >> 3, h = bh & 7;
    const int blbase = b << 12;
    float4 carry = make_float4(0.f, 0.f, 0.f, 0.f);
#pragma unroll
    for (int c = 0; c < NC; c++) {
        float* sp = g_S + ((size_t)(bh * NC + c) * HEADDIM + p) * D_STATE + n0;
        float4 SL = *(float4*)sp;
        *(float4*)sp = carry;
        float Pt = g_cumP[(blbase + c * CHUNK + CHUNK - 1) * NHEADS + h];
        carry.x = SL.x + Pt * carry.x;
        carry.y = SL.y + Pt * carry.y;
        carry.z = SL.z + Pt * carry.z;
        carry.w = SL.w + Pt * carry.w;
    }
}

// =====================================================================
// pass C (fixup): y_t += cumP_t * (C_t · S_in_c). Chunks 1..7 only.
// =====================================================================
__global__ __launch_bounds__(128) void fixup_kernel() {
    const int tid = threadIdx.x, lane = tid & 31, w = tid >> 5;
    const int pt = blockIdx.x;
    const int c  = blockIdx.y + 1;      // 1..7
    const int bh = blockIdx.z;
    const int b = bh >> 3, h = bh & 7;
    const int p0 = pt * 16 + w * 4, n0 = lane * 4;
    const int blbase = b << 12;
    const int t0 = c * CHUNK;

    uint64_t S00, S01, S10, S11, S20, S21, S30, S31;
    {
        const float* sp = g_S + ((size_t)(bh * NC + c) * HEADDIM + p0) * D_STATE + n0;
        ulonglong2 r0 = *(const ulonglong2*)(sp);
        ulonglong2 r1 = *(const ulonglong2*)(sp + D_STATE);
        ulonglong2 r2 = *(const ulonglong2*)(sp + 2 * D_STATE);
        ulonglong2 r3 = *(const ulonglong2*)(sp + 3 * D_STATE);
        S00 = r0.x; S01 = r0.y; S10 = r1.x; S11 = r1.y;
        S20 = r2.x; S21 = r2.y; S30 = r3.x; S31 = r3.y;
    }
    const float* Cp = g_conv + (size_t)blbase * CONV_DIM + D_INNER + D_STATE + n0;
    const float* Pp = g_cumP + blbase * NHEADS + h;
    float* Yp = g_y + (size_t)blbase * D_INNER + h * HEADDIM + p0;

#pragma unroll 2
    for (int t = t0; t < t0 + CHUNK; t++) {
        ulonglong2 Cv = *(const ulonglong2*)(Cp + (size_t)t * CONV_DIM);
        float cp = Pp[t * NHEADS];
        float v0, v1, v2, v3;
        { uint64_t u = fma2(S01, Cv.y, mul2(S00, Cv.x)); float lo, hi; unpack2(u, lo, hi); v0 = lo + hi; }
        { uint64_t u = fma2(S11, Cv.y, mul2(S10, Cv.x)); float lo, hi; unpack2(u, lo, hi); v1 = lo + hi; }
        { uint64_t u = fma2(S21, Cv.y, mul2(S20, Cv.x)); float lo, hi; unpack2(u, lo, hi); v2 = lo + hi; }
        { uint64_t u = fma2(S31, Cv.y, mul2(S30, Cv.x)); float lo, hi; unpack2(u, lo, hi); v3 = lo + hi; }
        float e = reduce4(v0, v1, v2, v3, lane);
        if (lane < 4) {
            float* yp = Yp + (size_t)t * D_INNER + lane;
            *yp += cp * e;
        }
    }
}

// =====================================================================
// mulnorm: y = y * silu(z); y = y * rsqrt(mean(y^2)+1e-5) * norm_w
// =====================================================================
__global__ __launch_bounds__(256) void mulnorm_kernel(const float* __restrict__ norm_w) {
    __shared__ float red[8];
    __shared__ float rinv;
    const int bl = blockIdx.x, tid = threadIdx.x;
    const int lane = tid & 31, w = tid >> 5;
    float4 yv = *(const float4*)(g_y + (size_t)bl * D_INNER + tid * 4);
    float4 zv = *(const float4*)(g_zx + (size_t)bl * D_IN_PROJ + tid * 4);
    float4 t;
    t.x = yv.x * (zv.x / (1.f + expf(-zv.x)));
    t.y = yv.y * (zv.y / (1.f + expf(-zv.y)));
    t.z = yv.z * (zv.z / (1.f + expf(-zv.z)));
    t.w = yv.w * (zv.w / (1.f + expf(-zv.w)));
    float ss = t.x * t.x + t.y * t.y + t.z * t.z + t.w * t.w;
#pragma unroll
    for (int off = 16; off > 0; off >>= 1) ss += __shfl_xor_sync(0xffffffffu, ss, off);
    if (lane == 0) red[w] = ss;
    __syncthreads();
    if (tid == 0) {
        float tot = 0.f;
#pragma unroll
        for (int i = 0; i < 8; i++) tot += red[i];
        rinv = rsqrtf(tot * (1.f / (float)D_INNER) + 1e-5f);
    }
    __syncthreads();
    const float r = rinv;
    float4 w4 = *(const float4*)(norm_w + tid * 4);
    t.x *= r * w4.x; t.y *= r * w4.y; t.z *= r * w4.z; t.w *= r * w4.w;
    *(float4*)(g_y + (size_t)bl * D_INNER + tid * 4) = t;
}

// =====================================================================
// GEMM2 (tf32 tensor core): out[b][d][l] = sum_e Wo[d][e]*y[bl][e] + x.
// =====================================================================
__global__ __launch_bounds__(256) void gemm2_kernel(const float* __restrict__ Wo,
                                                    const float* __restrict__ x,
                                                    float* __restrict__ out) {
    __shared__ uint32_t As[128][20];   // [d][k]
    __shared__ uint32_t Bs[128][20];   // [l][k]
    const int tid = threadIdx.x;
    const int l0 = blockIdx.x * 128;
    const int d0 = blockIdx.y * 128;
    const int b  = blockIdx.z;
    const float* yp = g_y + (size_t)(b * LSEQ + l0) * D_INNER;

    const int rb = tid >> 1;           // 0..127
    const int kb = (tid & 1) * 8;      // 0 or 8

    const int wid = tid >> 5, lane = tid & 31;
    const int wm = (wid >> 2) * 64;
    const int wn = (wid & 3) * 32;
    const int gid = lane >> 2, tig = lane & 3;

    float c[4][4][4];
#pragma unroll
    for (int i = 0; i < 4; i++)
#pragma unroll
        for (int j = 0; j < 4; j++)
#pragma unroll
            for (int q = 0; q < 4; q++) c[i][j][q] = 0.f;

    for (int k0 = 0; k0 < D_INNER; k0 += 16) {
        float4 av0 = *(const float4*)(Wo + (size_t)(d0 + rb) * D_INNER + k0 + kb);
        float4 av1 = *(const float4*)(Wo + (size_t)(d0 + rb) * D_INNER + k0 + kb + 4);
        float4 bv0 = *(const float4*)(yp + (size_t)rb * D_INNER + k0 + kb);
        float4 bv1 = *(const float4*)(yp + (size_t)rb * D_INNER + k0 + kb + 4);
        __syncthreads();
        {
            uint4 t;
            t.x = f2tf32(av0.x); t.y = f2tf32(av0.y); t.z = f2tf32(av0.z); t.w = f2tf32(av0.w);
            *(uint4*)&As[rb][kb] = t;
            t.x = f2tf32(av1.x); t.y = f2tf32(av1.y); t.z = f2tf32(av1.z); t.w = f2tf32(av1.w);
            *(uint4*)&As[rb][kb + 4] = t;
            t.x = f2tf32(bv0.x); t.y = f2tf32(bv0.y); t.z = f2tf32(bv0.z); t.w = f2tf32(bv0.w);
            *(uint4*)&Bs[rb][kb] = t;
            t.x = f2tf32(bv1.x); t.y = f2tf32(bv1.y); t.z = f2tf32(bv1.z); t.w = f2tf32(bv1.w);
            *(uint4*)&Bs[rb][kb + 4] = t;
        }
        __syncthreads();
#pragma unroll
        for (int kk = 0; kk < 16; kk += 8) {
            uint32_t af[4][4], bf[4][2];
#pragma unroll
            for (int mi = 0; mi < 4; mi++) {
                const int mr = wm + mi * 16 + gid;
                af[mi][0] = As[mr][kk + tig];
                af[mi][1] = As[mr + 8][kk + tig];
                af[mi][2] = As[mr][kk + tig + 4];
                af[mi][3] = As[mr + 8][kk + tig + 4];
            }
#pragma unroll
            for (int ni = 0; ni < 4; ni++) {
                const int nr = wn + ni * 8 + gid;
                bf[ni][0] = Bs[nr][kk + tig];
                bf[ni][1] = Bs[nr][kk + tig + 4];
            }
#pragma unroll
            for (int mi = 0; mi < 4; mi++)
#pragma unroll
                for (int ni = 0; ni < 4; ni++)
                    MMA_TF32(c[mi][ni], af[mi], bf[ni]);
        }
    }

    const size_t base = (size_t)b * DIM * LSEQ;
#pragma unroll
    for (int mi = 0; mi < 4; mi++) {
#pragma unroll
        for (int ni = 0; ni < 4; ni++) {
            const int d = d0 + wm + mi * 16 + gid;
            const int l = l0 + wn + ni * 8 + tig * 2;
            const size_t off0 = base + (size_t)d * LSEQ + l;
            const size_t off1 = off0 + (size_t)8 * LSEQ;
            float2 x0 = *(const float2*)(x + off0);
            float2 x1 = *(const float2*)(x + off1);
            float2 o0; o0.x = c[mi][ni][0] + x0.x; o0.y = c[mi][ni][1] + x0.y;
            float2 o1; o1.x = c[mi][ni][2] + x1.x; o1.y = c[mi][ni][3] + x1.y;
            *(float2*)(out + off0) = o0;
            *(float2*)(out + off1) = o1;
        }
    }
}

// =====================================================================
extern "C" void kernel_launch(void* const* d_in, const int* in_sizes, int n_in,
                              void* d_out, int out_size) {
    const float* x          = (const float*)d_in[0];
    const float* in_proj_w  = (const float*)d_in[1];
    const float* conv_w     = (const float*)d_in[2];
    const float* conv_b     = (const float*)d_in[3];
    const float* dt_bias    = (const float*)d_in[4];
    const float* A_log      = (const float*)d_in[5];
    const float* D_param    = (const float*)d_in[6];
    const float* norm_w     = (const float*)d_in[7];
    const float* out_proj_w = (const float*)d_in[8];
    float* out = (float*)d_out;

    // Launch order puts scan_kernel 4th so ncu's fixed capture lands on it.
    // 1. exact fp32 dt projection + softplus + dA
    dtprep_kernel<<<(NBL * NHEADS) / 256, 256>>>(x, in_proj_w, dt_bias, A_log);
    // 2. in_proj GEMM, tf32 tensor cores (cols 0..2303)
    gemm1_kernel<<<dim3(18, NBL / 128), 256>>>(x, in_proj_w);
    // 3. depthwise causal conv + SiLU
    conv_kernel<<<((size_t)NBL * CONV_DIM) / 256, 256>>>(conv_w, conv_b);
    // 4. chunked local scan (pass A, 8p/warp)
    scan_kernel<<<dim3(4, NC, 32), 128>>>(D_param);
    // 5. within-chunk cumprod of dA (only needed by passB/fixup)
    cumP_kernel<<<32, 256>>>();
    // 6. chunk carry recurrence (pass B)
    passB_kernel<<<(32 * HEADDIM * D_STATE / 4) / 256, 256>>>();
    // 7. carry fixup of y (pass C)
    fixup_kernel<<<dim3(8, NC - 1, 32), 128>>>();
    // 8. gate + RMSNorm
    mulnorm_kernel<<<NBL, 256>>>(norm_w);
    // 9. out_proj GEMM, tf32 tensor cores + residual, transposed store
    gemm2_kernel<<<dim3(LSEQ / 128, DIM / 128, BSZ), 256>>>(out_proj_w, x, out);
}